// round 2
// baseline (speedup 1.0000x reference)
#include <cuda_runtime.h>
#include <math.h>

#define N_NODES 50000
#define N_EDGES 600000
#define N_BONDS 600000
#define H 128
#define NH 8

// ---------------- scratch (device globals; no allocation allowed) ----------------
__device__ float    g_he0 [(size_t)N_EDGES * H];
__device__ float    g_agg [(size_t)N_EDGES * H];
__device__ float    g_agg2[(size_t)N_NODES * H];
__device__ float    g_beta[(size_t)N_EDGES * NH];
__device__ float    g_ex  [(size_t)N_EDGES * NH];
__device__ float    g_den [(size_t)N_NODES * NH];
__device__ unsigned g_nmax[(size_t)N_NODES * NH];

// ordered-uint transform for float atomic max
__device__ __forceinline__ unsigned fflip(float f) {
    unsigned u = __float_as_uint(f);
    return (u & 0x80000000u) ? ~u : (u | 0x80000000u);
}
__device__ __forceinline__ float funflip(unsigned u) {
    return __uint_as_float((u & 0x80000000u) ? (u ^ 0x80000000u) : ~u);
}

// ---------------- zero / init scratch ----------------
__global__ __launch_bounds__(256) void zero_scratch() {
    size_t idx = (size_t)blockIdx.x * 256 + threadIdx.x;
    if (idx < (size_t)N_EDGES * H) g_agg[idx] = 0.f;
    if (idx < (size_t)N_NODES * H) g_agg2[idx] = 0.f;
    if (idx < (size_t)N_NODES * NH) { g_den[idx] = 0.f; g_nmax[idx] = 0x007FFFFFu; /* fflip(-inf) */ }
}

// ---------------- GEMM A: gathered 3x128 concat (K=384), N=128 ----------------
// out[row,:] = relu( [S0[I0[row]] | S1[I1[row]] | S2[row]] @ [W0;W1;W2] + B0(+B1+B2) )
// if residual != null: out = residual[row,:] + relu(...)
__global__ __launch_bounds__(256) void gemm_gather3(
    int M,
    const float* __restrict__ S0, const int* __restrict__ I0,
    const float* __restrict__ S1, const int* __restrict__ I1,
    const float* __restrict__ S2,
    const float* __restrict__ W0, const float* __restrict__ W1, const float* __restrict__ W2,
    const float* __restrict__ B0, const float* __restrict__ B1, const float* __restrict__ B2,
    const float* __restrict__ residual,
    float* __restrict__ out)
{
    __shared__ float sA[64][17];
    __shared__ float sB[16][128];
    __shared__ int sI0[64], sI1[64];

    const int t = threadIdx.x;
    const int blockRow = blockIdx.x * 64;

    if (t < 64) {
        int r = blockRow + t;
        if (r >= M) r = M - 1;
        sI0[t] = I0[r];
        sI1[t] = I1[r];
    }
    __syncthreads();

    const int tx = t & 15;
    const int ty = t >> 4;
    const int r_ld = t >> 2;
    const int q = t & 3;
    const int s2row = (blockRow + r_ld < M) ? (blockRow + r_ld) : (M - 1);

    float acc[4][8];
#pragma unroll
    for (int i = 0; i < 4; ++i)
#pragma unroll
        for (int j = 0; j < 8; ++j) acc[i][j] = 0.f;

    for (int kt = 0; kt < 24; ++kt) {
        // ---- A tile (gathered) ----
        int gcol = kt * 16 + q * 4;
        int seg = gcol >> 7;
        int off = gcol & 127;
        const float* base;
        if (seg == 0)      base = S0 + (size_t)sI0[r_ld] * H;
        else if (seg == 1) base = S1 + (size_t)sI1[r_ld] * H;
        else               base = S2 + (size_t)s2row * H;
        float4 av = *(const float4*)(base + off);
        sA[r_ld][q * 4 + 0] = av.x;
        sA[r_ld][q * 4 + 1] = av.y;
        sA[r_ld][q * 4 + 2] = av.z;
        sA[r_ld][q * 4 + 3] = av.w;

        // ---- B tile ----
#pragma unroll
        for (int rep = 0; rep < 2; ++rep) {
            int f = t + rep * 256;
            int kl = f >> 5;
            int n = (f & 31) * 4;
            int gk = kt * 16 + kl;
            int sg = gk >> 7;
            int lk = gk & 127;
            const float* Wp = (sg == 0) ? W0 : ((sg == 1) ? W1 : W2);
            *(float4*)&sB[kl][n] = *(const float4*)(Wp + (size_t)lk * H + n);
        }
        __syncthreads();

#pragma unroll
        for (int k = 0; k < 16; ++k) {
            float a0 = sA[ty * 4 + 0][k];
            float a1 = sA[ty * 4 + 1][k];
            float a2 = sA[ty * 4 + 2][k];
            float a3 = sA[ty * 4 + 3][k];
            float4 bv0 = *(const float4*)&sB[k][tx * 8];
            float4 bv1 = *(const float4*)&sB[k][tx * 8 + 4];
            float bj[8] = {bv0.x, bv0.y, bv0.z, bv0.w, bv1.x, bv1.y, bv1.z, bv1.w};
#pragma unroll
            for (int j = 0; j < 8; ++j) {
                acc[0][j] = fmaf(a0, bj[j], acc[0][j]);
                acc[1][j] = fmaf(a1, bj[j], acc[1][j]);
                acc[2][j] = fmaf(a2, bj[j], acc[2][j]);
                acc[3][j] = fmaf(a3, bj[j], acc[3][j]);
            }
        }
        __syncthreads();
    }

    float bias[8];
#pragma unroll
    for (int j = 0; j < 8; ++j) {
        int col = tx * 8 + j;
        float b = B0[col];
        if (B1) b += B1[col];
        if (B2) b += B2[col];
        bias[j] = b;
    }
#pragma unroll
    for (int i = 0; i < 4; ++i) {
        int row = blockRow + ty * 4 + i;
        if (row >= M) continue;
#pragma unroll
        for (int j = 0; j < 8; ++j) {
            int col = tx * 8 + j;
            float v = fmaxf(acc[i][j] + bias[j], 0.f);
            if (residual) v += residual[(size_t)row * H + col];
            out[(size_t)row * H + col] = v;
        }
    }
}

// ---------------- GEMM B: aligned 2x128 concat (K=256), N=128, relu ----------------
__global__ __launch_bounds__(256) void gemm_cat2(
    int M,
    const float* __restrict__ A0,
    const float* __restrict__ A1c,
    const float* __restrict__ W,
    const float* __restrict__ Bb,
    float* __restrict__ out)
{
    __shared__ float sA[64][17];
    __shared__ float sB[16][128];

    const int t = threadIdx.x;
    const int blockRow = blockIdx.x * 64;
    const int tx = t & 15;
    const int ty = t >> 4;
    const int r_ld = t >> 2;
    const int q = t & 3;
    const int row_ld = (blockRow + r_ld < M) ? (blockRow + r_ld) : (M - 1);

    float acc[4][8];
#pragma unroll
    for (int i = 0; i < 4; ++i)
#pragma unroll
        for (int j = 0; j < 8; ++j) acc[i][j] = 0.f;

    for (int kt = 0; kt < 16; ++kt) {
        int gcol = kt * 16 + q * 4;
        int seg = gcol >> 7;
        int off = gcol & 127;
        const float* base = (seg ? A1c : A0) + (size_t)row_ld * H;
        float4 av = *(const float4*)(base + off);
        sA[r_ld][q * 4 + 0] = av.x;
        sA[r_ld][q * 4 + 1] = av.y;
        sA[r_ld][q * 4 + 2] = av.z;
        sA[r_ld][q * 4 + 3] = av.w;

#pragma unroll
        for (int rep = 0; rep < 2; ++rep) {
            int f = t + rep * 256;
            int kl = f >> 5;
            int n = (f & 31) * 4;
            int gk = kt * 16 + kl;
            *(float4*)&sB[kl][n] = *(const float4*)(W + (size_t)gk * H + n);
        }
        __syncthreads();

#pragma unroll
        for (int k = 0; k < 16; ++k) {
            float a0 = sA[ty * 4 + 0][k];
            float a1 = sA[ty * 4 + 1][k];
            float a2 = sA[ty * 4 + 2][k];
            float a3 = sA[ty * 4 + 3][k];
            float4 bv0 = *(const float4*)&sB[k][tx * 8];
            float4 bv1 = *(const float4*)&sB[k][tx * 8 + 4];
            float bj[8] = {bv0.x, bv0.y, bv0.z, bv0.w, bv1.x, bv1.y, bv1.z, bv1.w};
#pragma unroll
            for (int j = 0; j < 8; ++j) {
                acc[0][j] = fmaf(a0, bj[j], acc[0][j]);
                acc[1][j] = fmaf(a1, bj[j], acc[1][j]);
                acc[2][j] = fmaf(a2, bj[j], acc[2][j]);
                acc[3][j] = fmaf(a3, bj[j], acc[3][j]);
            }
        }
        __syncthreads();
    }

#pragma unroll
    for (int i = 0; i < 4; ++i) {
        int row = blockRow + ty * 4 + i;
        if (row >= M) continue;
#pragma unroll
        for (int j = 0; j < 8; ++j) {
            int col = tx * 8 + j;
            float v = fmaxf(acc[i][j] + Bb[col], 0.f);
            out[(size_t)row * H + col] = v;
        }
    }
}

// ---------------- bond scatter: agg[btgt] += he0[bsrc] * bond_attr ----------------
__global__ __launch_bounds__(256) void scatter_bond(
    const int* __restrict__ bsrc, const int* __restrict__ btgt,
    const float* __restrict__ battr)
{
    size_t idx = (size_t)blockIdx.x * 256 + threadIdx.x;
    int b = (int)(idx >> 7);
    int c = (int)(idx & 127);
    int s = bsrc[b];
    int g = btgt[b];
    atomicAdd(&g_agg[(size_t)g * H + c], g_he0[(size_t)s * H + c] * battr[idx]);
}

// ---------------- attention pass 1: beta + per-(node,head) max ----------------
__global__ __launch_bounds__(256) void attn_beta(
    const float* __restrict__ x,
    const int* __restrict__ src, const int* __restrict__ tgt,
    const float* __restrict__ he,
    const float* __restrict__ attnw, const float* __restrict__ attnb)
{
    int gt = blockIdx.x * 256 + threadIdx.x;
    int e = gt >> 5;
    int lane = gt & 31;
    int s = src[e];
    int g = tgt[e];
    int c = lane * 4;
    int d = c & 15;
    float4 xs = *(const float4*)(x + (size_t)s * H + c);
    float4 hh = *(const float4*)(he + (size_t)e * H + c);
    float4 xt = *(const float4*)(x + (size_t)g * H + c);
    float p = xs.x * hh.x * attnw[d]     + xt.x * attnw[16 + d]
            + xs.y * hh.y * attnw[d + 1] + xt.y * attnw[17 + d]
            + xs.z * hh.z * attnw[d + 2] + xt.z * attnw[18 + d]
            + xs.w * hh.w * attnw[d + 3] + xt.w * attnw[19 + d];
    p += __shfl_xor_sync(0xffffffffu, p, 1);
    p += __shfl_xor_sync(0xffffffffu, p, 2);
    if ((lane & 3) == 0) {
        int h = lane >> 2;
        float b = p + attnb[0];
        b = (b > 0.f) ? b : 0.01f * b;   // leaky_relu 0.01
        g_beta[(size_t)e * NH + h] = b;
        atomicMax(&g_nmax[(size_t)g * NH + h], fflip(b));
    }
}

// ---------------- attention pass 2: exp + denominator ----------------
__global__ __launch_bounds__(256) void attn_den(const int* __restrict__ tgt)
{
    int idx = blockIdx.x * 256 + threadIdx.x;
    if (idx >= N_EDGES * NH) return;
    int e = idx >> 3;
    int h = idx & 7;
    int g = tgt[e];
    float m = funflip(g_nmax[(size_t)g * NH + h]);
    float ex = expf(g_beta[idx] - m);
    g_ex[idx] = ex;
    atomicAdd(&g_den[(size_t)g * NH + h], ex);
}

// ---------------- attention pass 3: agg2[tgt] += alpha * xj ----------------
__global__ __launch_bounds__(256) void attn_scatter(
    const float* __restrict__ x,
    const int* __restrict__ src, const int* __restrict__ tgt,
    const float* __restrict__ he)
{
    size_t idx = (size_t)blockIdx.x * 256 + threadIdx.x;
    int e = (int)(idx >> 7);
    int c = (int)(idx & 127);
    int h = c >> 4;
    int s = src[e];
    int g = tgt[e];
    float alpha = g_ex[(size_t)e * NH + h] / (g_den[(size_t)g * NH + h] + 1e-16f);
    float val = alpha * x[(size_t)s * H + c] * he[idx];
    atomicAdd(&g_agg2[(size_t)g * H + c], val);
}

// ---------------- launch ----------------
extern "C" void kernel_launch(void* const* d_in, const int* in_sizes, int n_in,
                              void* d_out, int out_size)
{
    const float* x     = (const float*)d_in[0];
    const int*   ei    = (const int*)d_in[1];
    const float* eattr = (const float*)d_in[2];
    const int*   bei   = (const int*)d_in[3];
    const float* battr = (const float*)d_in[4];
    const float* W_n2e = (const float*)d_in[5];
    const float* b_n2e = (const float*)d_in[6];
    const float* A1w   = (const float*)d_in[7];
    const float* A1b   = (const float*)d_in[8];
    const float* A2w   = (const float*)d_in[9];
    const float* A2b   = (const float*)d_in[10];
    const float* A3w   = (const float*)d_in[11];
    const float* A3b   = (const float*)d_in[12];
    const float* Wc1w  = (const float*)d_in[13];
    const float* Wc1b  = (const float*)d_in[14];
    const float* attnw = (const float*)d_in[15];
    const float* attnb = (const float*)d_in[16];
    const float* Wc2w  = (const float*)d_in[17];
    const float* Wc2b  = (const float*)d_in[18];

    float* out    = (float*)d_out;
    float* out_hx = out;                                   // [N, H]
    float* out_he = out + (size_t)N_NODES * H;             // [E, H]
    float* out_ha = out_he + (size_t)N_EDGES * H;          // [E2, H]

    const int* src  = ei;
    const int* tgt  = ei + N_EDGES;
    const int* bsrc = bei;
    const int* btgt = bei + N_BONDS;

    float *p_he0, *p_agg, *p_agg2;
    cudaGetSymbolAddress((void**)&p_he0,  g_he0);
    cudaGetSymbolAddress((void**)&p_agg,  g_agg);
    cudaGetSymbolAddress((void**)&p_agg2, g_agg2);

    // 0) zero scratch accumulators / init maxes
    zero_scratch<<<(N_EDGES * H) / 256, 256>>>();

    // 1) he0 = relu(cat(x[src], x[tgt], edge_attr) @ W_n2e + b)
    gemm_gather3<<<N_EDGES / 64, 256>>>(
        N_EDGES, x, src, x, tgt, eattr,
        W_n2e, W_n2e + 128 * H, W_n2e + 256 * H,
        b_n2e, nullptr, nullptr, nullptr, p_he0);

    // 2) agg[btgt] += he0[bsrc] * bond_attr
    scatter_bond<<<(N_BONDS * H) / 256, 256>>>(bsrc, btgt, battr);

    // 3) he = relu(cat(he0, agg) @ Wc1 + b)
    gemm_cat2<<<N_EDGES / 64, 256>>>(N_EDGES, p_he0, p_agg, Wc1w, Wc1b, out_he);

    // 4) ha = bond_attr + relu(he0[bsrc]@A1 + he0[btgt]@A2 + bond_attr@A3 + b1+b2+b3)
    gemm_gather3<<<N_BONDS / 64, 256>>>(
        N_BONDS, p_he0, bsrc, p_he0, btgt, battr,
        A1w, A2w, A3w, A1b, A2b, A3b, battr, out_ha);

    // 5) attention: beta + segment max
    attn_beta<<<(N_EDGES * 32) / 256, 256>>>(x, src, tgt, out_he, attnw, attnb);

    // 6) exp + denominator
    attn_den<<<(N_EDGES * NH + 255) / 256, 256>>>(tgt);

    // 7) agg2[tgt] += alpha * (x[src] * he)
    attn_scatter<<<(N_EDGES * H) / 256, 256>>>(x, src, tgt, out_he);

    // 8) hx = relu(cat(x, agg2) @ Wc2 + b)
    gemm_cat2<<<(N_NODES + 63) / 64, 256>>>(N_NODES, x, p_agg2, Wc2w, Wc2b, out_hx);
}

// round 3
// speedup vs baseline: 1.5484x; 1.5484x over previous
#include <cuda_runtime.h>
#include <math.h>

#define N_NODES 50000
#define N_EDGES 600000
#define N_BONDS 600000
#define H 128
#define NH 8

// ---------------- scratch (device globals; no allocation allowed) ----------------
__device__ float    g_he0 [(size_t)N_EDGES * H];
__device__ float    g_agg [(size_t)N_EDGES * H];
__device__ float    g_agg2[(size_t)N_NODES * H];
__device__ float    g_beta[(size_t)N_EDGES * NH];
__device__ float    g_ex  [(size_t)N_EDGES * NH];
__device__ float    g_den [(size_t)N_NODES * NH];
__device__ unsigned g_nmax[(size_t)N_NODES * NH];

__device__ __forceinline__ unsigned fflip(float f) {
    unsigned u = __float_as_uint(f);
    return (u & 0x80000000u) ? ~u : (u | 0x80000000u);
}
__device__ __forceinline__ float funflip(unsigned u) {
    return __uint_as_float((u & 0x80000000u) ? (u ^ 0x80000000u) : ~u);
}

__global__ __launch_bounds__(256) void zero_scratch() {
    size_t idx = (size_t)blockIdx.x * 256 + threadIdx.x;
    if (idx < (size_t)N_EDGES * H) g_agg[idx] = 0.f;
    if (idx < (size_t)N_NODES * H) g_agg2[idx] = 0.f;
    if (idx < (size_t)N_NODES * NH) { g_den[idx] = 0.f; g_nmax[idx] = 0x007FFFFFu; }
}

// ==================================================================================
// GEMM v2: BM=128, BN=128, BK=16, 256 threads, 8x8 register tile, LDS.128 operands
// ==================================================================================

#define ASTRIDE 136   // padded row stride for transposed A smem (float units)

// ---- gathered 3x128 concat (K=384): out = [relu(cat @ W + bias)] (+ residual) ----
__global__ __launch_bounds__(256, 2) void gemm_gather3(
    int M,
    const float* __restrict__ S0, const int* __restrict__ I0,
    const float* __restrict__ S1, const int* __restrict__ I1,
    const float* __restrict__ S2,
    const float* __restrict__ W0, const float* __restrict__ W1, const float* __restrict__ W2,
    const float* __restrict__ B0, const float* __restrict__ B1, const float* __restrict__ B2,
    const float* __restrict__ residual,
    float* __restrict__ out)
{
    __shared__ float sAT[16][ASTRIDE];
    __shared__ float sB[16][128];
    __shared__ int sI0[128], sI1[128];

    const int t = threadIdx.x;
    const int blockRow = blockIdx.x * 128;

    if (t < 128) {
        int r = blockRow + t;
        if (r >= M) r = M - 1;
        sI0[t] = I0[r];
        sI1[t] = I1[r];
    }
    __syncthreads();

    const int tx = t & 15;          // N direction: 16 * 8 = 128
    const int ty = t >> 4;          // M direction: 16 * 8 = 128
    const int rA = t >> 1;          // A-load row 0..127
    const int qA = t & 1;           // A-load col half (8 floats each)
    const int kB = t >> 4;          // B-load k row 0..15
    const int nB = (t & 15) * 8;    // B-load col
    const int rowS2 = (blockRow + rA < M) ? (blockRow + rA) : (M - 1);

    float acc[8][8];
#pragma unroll
    for (int i = 0; i < 8; ++i)
#pragma unroll
        for (int j = 0; j < 8; ++j) acc[i][j] = 0.f;

    for (int kt = 0; kt < 24; ++kt) {
        // ---- A tile: gather 128 rows x 16 cols, store transposed ----
        {
            int gc = kt * 16 + qA * 8;
            int seg = gc >> 7;
            int off = gc & 127;
            const float* base;
            if (seg == 0)      base = S0 + (size_t)sI0[rA] * H;
            else if (seg == 1) base = S1 + (size_t)sI1[rA] * H;
            else               base = S2 + (size_t)rowS2 * H;
            float4 v0 = *(const float4*)(base + off);
            float4 v1 = *(const float4*)(base + off + 4);
            int kb = qA * 8;
            sAT[kb + 0][rA] = v0.x; sAT[kb + 1][rA] = v0.y;
            sAT[kb + 2][rA] = v0.z; sAT[kb + 3][rA] = v0.w;
            sAT[kb + 4][rA] = v1.x; sAT[kb + 5][rA] = v1.y;
            sAT[kb + 6][rA] = v1.z; sAT[kb + 7][rA] = v1.w;
        }
        // ---- B tile: 16 x 128 ----
        {
            int gk = kt * 16 + kB;
            int sg = gk >> 7;
            int lk = gk & 127;
            const float* Wp = (sg == 0) ? W0 : ((sg == 1) ? W1 : W2);
            float4 b0 = *(const float4*)(Wp + (size_t)lk * H + nB);
            float4 b1 = *(const float4*)(Wp + (size_t)lk * H + nB + 4);
            *(float4*)&sB[kB][nB] = b0;
            *(float4*)&sB[kB][nB + 4] = b1;
        }
        __syncthreads();

#pragma unroll
        for (int k = 0; k < 16; ++k) {
            float4 a0 = *(const float4*)&sAT[k][ty * 8];
            float4 a1 = *(const float4*)&sAT[k][ty * 8 + 4];
            float4 b0 = *(const float4*)&sB[k][tx * 8];
            float4 b1 = *(const float4*)&sB[k][tx * 8 + 4];
            float av[8] = {a0.x, a0.y, a0.z, a0.w, a1.x, a1.y, a1.z, a1.w};
            float bv[8] = {b0.x, b0.y, b0.z, b0.w, b1.x, b1.y, b1.z, b1.w};
#pragma unroll
            for (int i = 0; i < 8; ++i)
#pragma unroll
                for (int j = 0; j < 8; ++j)
                    acc[i][j] = fmaf(av[i], bv[j], acc[i][j]);
        }
        __syncthreads();
    }

    float bias[8];
#pragma unroll
    for (int j = 0; j < 8; ++j) {
        int col = tx * 8 + j;
        float b = B0[col];
        if (B1) b += B1[col];
        if (B2) b += B2[col];
        bias[j] = b;
    }
#pragma unroll
    for (int i = 0; i < 8; ++i) {
        int row = blockRow + ty * 8 + i;
        if (row >= M) continue;
        float v[8];
#pragma unroll
        for (int j = 0; j < 8; ++j) v[j] = fmaxf(acc[i][j] + bias[j], 0.f);
        if (residual) {
            float4 r0 = *(const float4*)(residual + (size_t)row * H + tx * 8);
            float4 r1 = *(const float4*)(residual + (size_t)row * H + tx * 8 + 4);
            v[0] += r0.x; v[1] += r0.y; v[2] += r0.z; v[3] += r0.w;
            v[4] += r1.x; v[5] += r1.y; v[6] += r1.z; v[7] += r1.w;
        }
        *(float4*)(out + (size_t)row * H + tx * 8)     = make_float4(v[0], v[1], v[2], v[3]);
        *(float4*)(out + (size_t)row * H + tx * 8 + 4) = make_float4(v[4], v[5], v[6], v[7]);
    }
}

// ---- aligned 2x128 concat (K=256): out = relu(cat(A0,A1) @ W + bias) ----
__global__ __launch_bounds__(256, 2) void gemm_cat2(
    int M,
    const float* __restrict__ A0,
    const float* __restrict__ A1c,
    const float* __restrict__ W,
    const float* __restrict__ Bb,
    float* __restrict__ out)
{
    __shared__ float sAT[16][ASTRIDE];
    __shared__ float sB[16][128];

    const int t = threadIdx.x;
    const int blockRow = blockIdx.x * 128;
    const int tx = t & 15;
    const int ty = t >> 4;
    const int rA = t >> 1;
    const int qA = t & 1;
    const int kB = t >> 4;
    const int nB = (t & 15) * 8;
    const int rowA = (blockRow + rA < M) ? (blockRow + rA) : (M - 1);

    float acc[8][8];
#pragma unroll
    for (int i = 0; i < 8; ++i)
#pragma unroll
        for (int j = 0; j < 8; ++j) acc[i][j] = 0.f;

    for (int kt = 0; kt < 16; ++kt) {
        {
            int gc = kt * 16 + qA * 8;
            int seg = gc >> 7;
            int off = gc & 127;
            const float* base = (seg ? A1c : A0) + (size_t)rowA * H;
            float4 v0 = *(const float4*)(base + off);
            float4 v1 = *(const float4*)(base + off + 4);
            int kb = qA * 8;
            sAT[kb + 0][rA] = v0.x; sAT[kb + 1][rA] = v0.y;
            sAT[kb + 2][rA] = v0.z; sAT[kb + 3][rA] = v0.w;
            sAT[kb + 4][rA] = v1.x; sAT[kb + 5][rA] = v1.y;
            sAT[kb + 6][rA] = v1.z; sAT[kb + 7][rA] = v1.w;
        }
        {
            int gk = kt * 16 + kB;
            float4 b0 = *(const float4*)(W + (size_t)gk * H + nB);
            float4 b1 = *(const float4*)(W + (size_t)gk * H + nB + 4);
            *(float4*)&sB[kB][nB] = b0;
            *(float4*)&sB[kB][nB + 4] = b1;
        }
        __syncthreads();

#pragma unroll
        for (int k = 0; k < 16; ++k) {
            float4 a0 = *(const float4*)&sAT[k][ty * 8];
            float4 a1 = *(const float4*)&sAT[k][ty * 8 + 4];
            float4 b0 = *(const float4*)&sB[k][tx * 8];
            float4 b1 = *(const float4*)&sB[k][tx * 8 + 4];
            float av[8] = {a0.x, a0.y, a0.z, a0.w, a1.x, a1.y, a1.z, a1.w};
            float bv[8] = {b0.x, b0.y, b0.z, b0.w, b1.x, b1.y, b1.z, b1.w};
#pragma unroll
            for (int i = 0; i < 8; ++i)
#pragma unroll
                for (int j = 0; j < 8; ++j)
                    acc[i][j] = fmaf(av[i], bv[j], acc[i][j]);
        }
        __syncthreads();
    }

    float bias[8];
#pragma unroll
    for (int j = 0; j < 8; ++j) bias[j] = Bb[tx * 8 + j];
#pragma unroll
    for (int i = 0; i < 8; ++i) {
        int row = blockRow + ty * 8 + i;
        if (row >= M) continue;
        float v[8];
#pragma unroll
        for (int j = 0; j < 8; ++j) v[j] = fmaxf(acc[i][j] + bias[j], 0.f);
        *(float4*)(out + (size_t)row * H + tx * 8)     = make_float4(v[0], v[1], v[2], v[3]);
        *(float4*)(out + (size_t)row * H + tx * 8 + 4) = make_float4(v[4], v[5], v[6], v[7]);
    }
}

// ---------------- bond scatter: agg[btgt] += he0[bsrc] * bond_attr ----------------
__global__ __launch_bounds__(256) void scatter_bond(
    const int* __restrict__ bsrc, const int* __restrict__ btgt,
    const float* __restrict__ battr)
{
    size_t idx = (size_t)blockIdx.x * 256 + threadIdx.x;
    int b = (int)(idx >> 7);
    int c = (int)(idx & 127);
    int s = bsrc[b];
    int g = btgt[b];
    atomicAdd(&g_agg[(size_t)g * H + c], g_he0[(size_t)s * H + c] * battr[idx]);
}

// ---------------- attention pass 1: beta + per-(node,head) max ----------------
__global__ __launch_bounds__(256) void attn_beta(
    const float* __restrict__ x,
    const int* __restrict__ src, const int* __restrict__ tgt,
    const float* __restrict__ he,
    const float* __restrict__ attnw, const float* __restrict__ attnb)
{
    int gt = blockIdx.x * 256 + threadIdx.x;
    int e = gt >> 5;
    int lane = gt & 31;
    int s = src[e];
    int g = tgt[e];
    int c = lane * 4;
    int d = c & 15;
    float4 xs = *(const float4*)(x + (size_t)s * H + c);
    float4 hh = *(const float4*)(he + (size_t)e * H + c);
    float4 xt = *(const float4*)(x + (size_t)g * H + c);
    float p = xs.x * hh.x * attnw[d]     + xt.x * attnw[16 + d]
            + xs.y * hh.y * attnw[d + 1] + xt.y * attnw[17 + d]
            + xs.z * hh.z * attnw[d + 2] + xt.z * attnw[18 + d]
            + xs.w * hh.w * attnw[d + 3] + xt.w * attnw[19 + d];
    p += __shfl_xor_sync(0xffffffffu, p, 1);
    p += __shfl_xor_sync(0xffffffffu, p, 2);
    if ((lane & 3) == 0) {
        int h = lane >> 2;
        float b = p + attnb[0];
        b = (b > 0.f) ? b : 0.01f * b;
        g_beta[(size_t)e * NH + h] = b;
        atomicMax(&g_nmax[(size_t)g * NH + h], fflip(b));
    }
}

// ---------------- attention pass 2: exp + denominator ----------------
__global__ __launch_bounds__(256) void attn_den(const int* __restrict__ tgt)
{
    int idx = blockIdx.x * 256 + threadIdx.x;
    if (idx >= N_EDGES * NH) return;
    int e = idx >> 3;
    int h = idx & 7;
    int g = tgt[e];
    float m = funflip(g_nmax[(size_t)g * NH + h]);
    float ex = expf(g_beta[idx] - m);
    g_ex[idx] = ex;
    atomicAdd(&g_den[(size_t)g * NH + h], ex);
}

// ---------------- attention pass 3: agg2[tgt] += alpha * xj ----------------
__global__ __launch_bounds__(256) void attn_scatter(
    const float* __restrict__ x,
    const int* __restrict__ src, const int* __restrict__ tgt,
    const float* __restrict__ he)
{
    size_t idx = (size_t)blockIdx.x * 256 + threadIdx.x;
    int e = (int)(idx >> 7);
    int c = (int)(idx & 127);
    int h = c >> 4;
    int s = src[e];
    int g = tgt[e];
    float alpha = g_ex[(size_t)e * NH + h] / (g_den[(size_t)g * NH + h] + 1e-16f);
    float val = alpha * x[(size_t)s * H + c] * he[idx];
    atomicAdd(&g_agg2[(size_t)g * H + c], val);
}

// ---------------- launch ----------------
extern "C" void kernel_launch(void* const* d_in, const int* in_sizes, int n_in,
                              void* d_out, int out_size)
{
    const float* x     = (const float*)d_in[0];
    const int*   ei    = (const int*)d_in[1];
    const float* eattr = (const float*)d_in[2];
    const int*   bei   = (const int*)d_in[3];
    const float* battr = (const float*)d_in[4];
    const float* W_n2e = (const float*)d_in[5];
    const float* b_n2e = (const float*)d_in[6];
    const float* A1w   = (const float*)d_in[7];
    const float* A1b   = (const float*)d_in[8];
    const float* A2w   = (const float*)d_in[9];
    const float* A2b   = (const float*)d_in[10];
    const float* A3w   = (const float*)d_in[11];
    const float* A3b   = (const float*)d_in[12];
    const float* Wc1w  = (const float*)d_in[13];
    const float* Wc1b  = (const float*)d_in[14];
    const float* attnw = (const float*)d_in[15];
    const float* attnb = (const float*)d_in[16];
    const float* Wc2w  = (const float*)d_in[17];
    const float* Wc2b  = (const float*)d_in[18];

    float* out    = (float*)d_out;
    float* out_hx = out;
    float* out_he = out + (size_t)N_NODES * H;
    float* out_ha = out_he + (size_t)N_EDGES * H;

    const int* src  = ei;
    const int* tgt  = ei + N_EDGES;
    const int* bsrc = bei;
    const int* btgt = bei + N_BONDS;

    float *p_he0, *p_agg, *p_agg2;
    cudaGetSymbolAddress((void**)&p_he0,  g_he0);
    cudaGetSymbolAddress((void**)&p_agg,  g_agg);
    cudaGetSymbolAddress((void**)&p_agg2, g_agg2);

    zero_scratch<<<(N_EDGES * H) / 256, 256>>>();

    // 1) he0 = relu(cat(x[src], x[tgt], edge_attr) @ W_n2e + b)
    gemm_gather3<<<(N_EDGES + 127) / 128, 256>>>(
        N_EDGES, x, src, x, tgt, eattr,
        W_n2e, W_n2e + 128 * H, W_n2e + 256 * H,
        b_n2e, nullptr, nullptr, nullptr, p_he0);

    // 2) agg[btgt] += he0[bsrc] * bond_attr
    scatter_bond<<<(N_BONDS * H) / 256, 256>>>(bsrc, btgt, battr);

    // 3) he = relu(cat(he0, agg) @ Wc1 + b)
    gemm_cat2<<<(N_EDGES + 127) / 128, 256>>>(N_EDGES, p_he0, p_agg, Wc1w, Wc1b, out_he);

    // 4) ha = bond_attr + relu(he0[bsrc]@A1 + he0[btgt]@A2 + bond_attr@A3 + biases)
    gemm_gather3<<<(N_BONDS + 127) / 128, 256>>>(
        N_BONDS, p_he0, bsrc, p_he0, btgt, battr,
        A1w, A2w, A3w, A1b, A2b, A3b, battr, out_ha);

    // 5) beta + segment max
    attn_beta<<<(N_EDGES * 32) / 256, 256>>>(x, src, tgt, out_he, attnw, attnb);

    // 6) exp + denominator
    attn_den<<<(N_EDGES * NH + 255) / 256, 256>>>(tgt);

    // 7) agg2[tgt] += alpha * (x[src] * he)
    attn_scatter<<<(N_EDGES * H) / 256, 256>>>(x, src, tgt, out_he);

    // 8) hx = relu(cat(x, agg2) @ Wc2 + b)
    gemm_cat2<<<(N_NODES + 127) / 128, 256>>>(N_NODES, x, p_agg2, Wc2w, Wc2b, out_hx);
}

// round 5
// speedup vs baseline: 1.8141x; 1.1716x over previous
#include <cuda_runtime.h>
#include <cuda_bf16.h>
#include <math.h>
#include <stdint.h>

#define N_NODES 50000
#define N_EDGES 600000
#define N_BONDS 600000
#define H 128
#define NH 8

// ---------------- scratch ----------------
__device__ float    g_he0 [(size_t)N_EDGES * H];
__device__ float    g_agg [(size_t)N_EDGES * H];
__device__ float    g_agg2[(size_t)N_NODES * H];
__device__ float    g_beta[(size_t)N_EDGES * NH];
__device__ float    g_ex  [(size_t)N_EDGES * NH];
__device__ float    g_den [(size_t)N_NODES * NH];
__device__ unsigned g_nmax[(size_t)N_NODES * NH];
// 10 weight 128x128 K-slices, each stored transposed [n][k] bf16: [hi 32KB][lo 32KB]
__device__ unsigned char g_wsplit[10 * 2 * 32768];

__device__ __forceinline__ unsigned fflip(float f) {
    unsigned u = __float_as_uint(f);
    return (u & 0x80000000u) ? ~u : (u | 0x80000000u);
}
__device__ __forceinline__ float funflip(unsigned u) {
    return __uint_as_float((u & 0x80000000u) ? (u ^ 0x80000000u) : ~u);
}
__device__ __forceinline__ void split_bf16(float v, unsigned short& hi, unsigned short& lo) {
    __nv_bfloat16 h = __float2bfloat16_rn(v);
    float r = v - __bfloat162float(h);
    __nv_bfloat16 l = __float2bfloat16_rn(r);
    hi = __bfloat16_as_ushort(h);
    lo = __bfloat16_as_ushort(l);
}

__device__ __forceinline__ void mma_bf16(float* d, const unsigned* a, unsigned b0, unsigned b1) {
    asm volatile(
        "mma.sync.aligned.m16n8k16.row.col.f32.bf16.bf16.f32 "
        "{%0,%1,%2,%3}, {%4,%5,%6,%7}, {%8,%9}, {%0,%1,%2,%3};"
        : "+f"(d[0]), "+f"(d[1]), "+f"(d[2]), "+f"(d[3])
        : "r"(a[0]), "r"(a[1]), "r"(a[2]), "r"(a[3]), "r"(b0), "r"(b1));
}

__global__ __launch_bounds__(256) void zero_scratch() {
    size_t idx = (size_t)blockIdx.x * 256 + threadIdx.x;
    if (idx < (size_t)N_EDGES * H) g_agg[idx] = 0.f;
    if (idx < (size_t)N_NODES * H) g_agg2[idx] = 0.f;
    if (idx < (size_t)N_NODES * NH) { g_den[idx] = 0.f; g_nmax[idx] = 0x007FFFFFu; }
}

// ---------------- weight prep: fp32 W[128k][128n] slice -> transposed bf16 hi/lo [n][k] ----------------
__global__ __launch_bounds__(256) void prep_wslice(
    const float* __restrict__ W, unsigned short* __restrict__ dsthi, unsigned short* __restrict__ dstlo)
{
    int e = blockIdx.x * 256 + threadIdx.x;   // 0..16383
    int k = e >> 7;
    int n = e & 127;
    float v = W[k * 128 + n];
    unsigned short h, l;
    split_bf16(v, h, l);
    dsthi[n * 128 + k] = h;
    dstlo[n * 128 + k] = l;
}

// ==================================================================================
// split-bf16 HMMA GEMM: BM=128, BN=128, BK=32, 256 threads (8 warps, warp 32x64)
// out[row,:] = relu( cat(seg0..segNSEG-1)[row,:] @ W + bias ) (+ residual)
// ==================================================================================
#define SAPAD 36   // bf16 row stride for smem tiles

template<int NSEG>
__global__ __launch_bounds__(256, 1)
void mma_gemm(
    int M,
    const float* __restrict__ S0, const int* __restrict__ I0,
    const float* __restrict__ S1, const int* __restrict__ I1,
    const float* __restrict__ S2,
    const unsigned char* __restrict__ wsl,     // NSEG slices: [hi 32KB][lo 32KB] each
    const float* __restrict__ B0, const float* __restrict__ B1, const float* __restrict__ B2,
    const float* __restrict__ residual,
    float* __restrict__ out)
{
    __shared__ __align__(16) unsigned short sA[2][128][SAPAD];
    __shared__ __align__(16) unsigned short sB[2][128][SAPAD];
    __shared__ int sI0[128], sI1[128];
    __shared__ float sbias[128];

    const int t = threadIdx.x;
    const int lane = t & 31;
    const int wid = t >> 5;
    const int warp_m = wid & 3;          // 4 warps along M (32 rows each)
    const int warp_n = wid >> 2;         // 2 warps along N (64 cols each)
    const int blockRow = blockIdx.x * 128;

    if (t < 128) {
        int r = blockRow + t;
        if (r >= M) r = M - 1;
        sI0[t] = I0 ? I0[r] : r;
        sI1[t] = I1 ? I1[r] : r;
        float b = B0[t];
        if (B1) b += B1[t];
        if (B2) b += B2[t];
        sbias[t] = b;
    }
    __syncthreads();

    // A-loader role: row = t>>1, seg half = t&1 (16 floats each)
    const int arow = t >> 1;
    const int aseg = t & 1;
    const int arow_clamped = (blockRow + arow < M) ? (blockRow + arow) : (M - 1);
    // B-loader role: h = t>>7 (hi/lo), n = t&127
    const int bh = t >> 7;
    const int bn = t & 127;

    float d[2][8][4];
#pragma unroll
    for (int mt = 0; mt < 2; ++mt)
#pragma unroll
        for (int nt = 0; nt < 8; ++nt)
#pragma unroll
            for (int c = 0; c < 4; ++c) d[mt][nt][c] = 0.f;

    const int NITER = NSEG * 4;
    for (int kt = 0; kt < NITER; ++kt) {
        const int s = kt >> 2;
        // ---- load + split A: 128 rows x 32 k ----
        {
            const float* rp;
            if (s == 0)            rp = S0 + (size_t)sI0[arow] * H;
            else if (s == 1)       rp = S1 + (size_t)sI1[arow] * H;
            else                   rp = S2 + (size_t)arow_clamped * H;
            int kloc = (kt & 3) * 32 + aseg * 16;
            float fl[16];
#pragma unroll
            for (int i = 0; i < 4; ++i) {
                float4 v = *(const float4*)(rp + kloc + i * 4);
                fl[i * 4 + 0] = v.x; fl[i * 4 + 1] = v.y;
                fl[i * 4 + 2] = v.z; fl[i * 4 + 3] = v.w;
            }
            unsigned short* ah = &sA[0][arow][aseg * 16];
            unsigned short* al = &sA[1][arow][aseg * 16];
#pragma unroll
            for (int i = 0; i < 16; ++i) {
                unsigned short h, l;
                split_bf16(fl[i], h, l);
                ah[i] = h;
                al[i] = l;
            }
        }
        // ---- load B slice columns: [128 n][32 k] hi/lo ----
        {
            const unsigned char* src = wsl + (size_t)s * 65536 + (size_t)bh * 32768
                                     + (size_t)bn * 256 + (size_t)(kt & 3) * 64;
            uint4 v0 = *(const uint4*)(src);
            uint4 v1 = *(const uint4*)(src + 16);
            uint4 v2 = *(const uint4*)(src + 32);
            uint4 v3 = *(const uint4*)(src + 48);
            unsigned* dst = (unsigned*)&sB[bh][bn][0];
            dst[0] = v0.x; dst[1] = v0.y; dst[2] = v0.z; dst[3] = v0.w;
            dst[4] = v1.x; dst[5] = v1.y; dst[6] = v1.z; dst[7] = v1.w;
            dst[8] = v2.x; dst[9] = v2.y; dst[10] = v2.z; dst[11] = v2.w;
            dst[12] = v3.x; dst[13] = v3.y; dst[14] = v3.z; dst[15] = v3.w;
        }
        __syncthreads();

        // ---- MMA: 2 k16 steps ----
#pragma unroll
        for (int ks = 0; ks < 2; ++ks) {
            const int kc = ks * 16 + (lane & 3) * 2;
            unsigned ah[2][4], al[2][4];
#pragma unroll
            for (int mt = 0; mt < 2; ++mt) {
                int r = warp_m * 32 + mt * 16 + (lane >> 2);
                ah[mt][0] = *(const unsigned*)&sA[0][r][kc];
                ah[mt][1] = *(const unsigned*)&sA[0][r + 8][kc];
                ah[mt][2] = *(const unsigned*)&sA[0][r][kc + 8];
                ah[mt][3] = *(const unsigned*)&sA[0][r + 8][kc + 8];
                al[mt][0] = *(const unsigned*)&sA[1][r][kc];
                al[mt][1] = *(const unsigned*)&sA[1][r + 8][kc];
                al[mt][2] = *(const unsigned*)&sA[1][r][kc + 8];
                al[mt][3] = *(const unsigned*)&sA[1][r + 8][kc + 8];
            }
#pragma unroll
            for (int nt = 0; nt < 8; ++nt) {
                int n = warp_n * 64 + nt * 8 + (lane >> 2);
                unsigned bh0 = *(const unsigned*)&sB[0][n][kc];
                unsigned bh1 = *(const unsigned*)&sB[0][n][kc + 8];
                unsigned bl0 = *(const unsigned*)&sB[1][n][kc];
                unsigned bl1 = *(const unsigned*)&sB[1][n][kc + 8];
#pragma unroll
                for (int mt = 0; mt < 2; ++mt) {
                    mma_bf16(d[mt][nt], ah[mt], bh0, bh1);
                    mma_bf16(d[mt][nt], al[mt], bh0, bh1);
                    mma_bf16(d[mt][nt], ah[mt], bl0, bl1);
                }
            }
        }
        __syncthreads();
    }

    // ---- epilogue ----
#pragma unroll
    for (int mt = 0; mt < 2; ++mt) {
#pragma unroll
        for (int half = 0; half < 2; ++half) {
            int r = warp_m * 32 + mt * 16 + (lane >> 2) + half * 8;
            int grow = blockRow + r;
            if (grow >= M) continue;
#pragma unroll
            for (int nt = 0; nt < 8; ++nt) {
                int gc = warp_n * 64 + nt * 8 + (lane & 3) * 2;
                float v0 = d[mt][nt][half * 2 + 0] + sbias[gc];
                float v1 = d[mt][nt][half * 2 + 1] + sbias[gc + 1];
                v0 = fmaxf(v0, 0.f);
                v1 = fmaxf(v1, 0.f);
                if (residual) {
                    float2 rr = *(const float2*)(residual + (size_t)grow * H + gc);
                    v0 += rr.x;
                    v1 += rr.y;
                }
                *(float2*)(out + (size_t)grow * H + gc) = make_float2(v0, v1);
            }
        }
    }
}

// ---------------- bond scatter ----------------
__global__ __launch_bounds__(256) void scatter_bond(
    const int* __restrict__ bsrc, const int* __restrict__ btgt,
    const float* __restrict__ battr)
{
    size_t idx = (size_t)blockIdx.x * 256 + threadIdx.x;
    int b = (int)(idx >> 7);
    int c = (int)(idx & 127);
    int s = bsrc[b];
    int g = btgt[b];
    atomicAdd(&g_agg[(size_t)g * H + c], g_he0[(size_t)s * H + c] * battr[idx]);
}

// ---------------- attention pass 1 ----------------
__global__ __launch_bounds__(256) void attn_beta(
    const float* __restrict__ x,
    const int* __restrict__ src, const int* __restrict__ tgt,
    const float* __restrict__ he,
    const float* __restrict__ attnw, const float* __restrict__ attnb)
{
    int gt = blockIdx.x * 256 + threadIdx.x;
    int e = gt >> 5;
    int lane = gt & 31;
    int s = src[e];
    int g = tgt[e];
    int c = lane * 4;
    int d = c & 15;
    float4 xs = *(const float4*)(x + (size_t)s * H + c);
    float4 hh = *(const float4*)(he + (size_t)e * H + c);
    float4 xt = *(const float4*)(x + (size_t)g * H + c);
    float p = xs.x * hh.x * attnw[d]     + xt.x * attnw[16 + d]
            + xs.y * hh.y * attnw[d + 1] + xt.y * attnw[17 + d]
            + xs.z * hh.z * attnw[d + 2] + xt.z * attnw[18 + d]
            + xs.w * hh.w * attnw[d + 3] + xt.w * attnw[19 + d];
    p += __shfl_xor_sync(0xffffffffu, p, 1);
    p += __shfl_xor_sync(0xffffffffu, p, 2);
    if ((lane & 3) == 0) {
        int h = lane >> 2;
        float b = p + attnb[0];
        b = (b > 0.f) ? b : 0.01f * b;
        g_beta[(size_t)e * NH + h] = b;
        atomicMax(&g_nmax[(size_t)g * NH + h], fflip(b));
    }
}

// ---------------- attention pass 2 ----------------
__global__ __launch_bounds__(256) void attn_den(const int* __restrict__ tgt)
{
    int idx = blockIdx.x * 256 + threadIdx.x;
    if (idx >= N_EDGES * NH) return;
    int e = idx >> 3;
    int h = idx & 7;
    int g = tgt[e];
    float m = funflip(g_nmax[(size_t)g * NH + h]);
    float ex = expf(g_beta[idx] - m);
    g_ex[idx] = ex;
    atomicAdd(&g_den[(size_t)g * NH + h], ex);
}

// ---------------- attention pass 3 ----------------
__global__ __launch_bounds__(256) void attn_scatter(
    const float* __restrict__ x,
    const int* __restrict__ src, const int* __restrict__ tgt,
    const float* __restrict__ he)
{
    size_t idx = (size_t)blockIdx.x * 256 + threadIdx.x;
    int e = (int)(idx >> 7);
    int c = (int)(idx & 127);
    int h = c >> 4;
    int s = src[e];
    int g = tgt[e];
    float alpha = g_ex[(size_t)e * NH + h] / (g_den[(size_t)g * NH + h] + 1e-16f);
    float val = alpha * x[(size_t)s * H + c] * he[idx];
    atomicAdd(&g_agg2[(size_t)g * H + c], val);
}

// ---------------- launch ----------------
extern "C" void kernel_launch(void* const* d_in, const int* in_sizes, int n_in,
                              void* d_out, int out_size)
{
    const float* x     = (const float*)d_in[0];
    const int*   ei    = (const int*)d_in[1];
    const float* eattr = (const float*)d_in[2];
    const int*   bei   = (const int*)d_in[3];
    const float* battr = (const float*)d_in[4];
    const float* W_n2e = (const float*)d_in[5];
    const float* b_n2e = (const float*)d_in[6];
    const float* A1w   = (const float*)d_in[7];
    const float* A1b   = (const float*)d_in[8];
    const float* A2w   = (const float*)d_in[9];
    const float* A2b   = (const float*)d_in[10];
    const float* A3w   = (const float*)d_in[11];
    const float* A3b   = (const float*)d_in[12];
    const float* Wc1w  = (const float*)d_in[13];
    const float* Wc1b  = (const float*)d_in[14];
    const float* attnw = (const float*)d_in[15];
    const float* attnb = (const float*)d_in[16];
    const float* Wc2w  = (const float*)d_in[17];
    const float* Wc2b  = (const float*)d_in[18];

    float* out    = (float*)d_out;
    float* out_hx = out;
    float* out_he = out + (size_t)N_NODES * H;
    float* out_ha = out_he + (size_t)N_EDGES * H;

    const int* src  = ei;
    const int* tgt  = ei + N_EDGES;
    const int* bsrc = bei;
    const int* btgt = bei + N_BONDS;

    float *p_he0, *p_agg, *p_agg2;
    unsigned char* p_w;
    cudaGetSymbolAddress((void**)&p_he0,  g_he0);
    cudaGetSymbolAddress((void**)&p_agg,  g_agg);
    cudaGetSymbolAddress((void**)&p_agg2, g_agg2);
    cudaGetSymbolAddress((void**)&p_w,    g_wsplit);

    // weight slice table: [0..2]=W_n2e, [3..4]=Wc1, [5]=A1, [6]=A2, [7]=A3, [8..9]=Wc2
    const float* wsrc[10] = {
        W_n2e, W_n2e + 128 * H, W_n2e + 256 * H,
        Wc1w, Wc1w + 128 * H,
        A1w, A2w, A3w,
        Wc2w, Wc2w + 128 * H
    };
    for (int i = 0; i < 10; ++i)
        prep_wslice<<<64, 256>>>(wsrc[i],
            (unsigned short*)(p_w + (size_t)i * 65536),
            (unsigned short*)(p_w + (size_t)i * 65536 + 32768));

    zero_scratch<<<(N_EDGES * H) / 256, 256>>>();

    // 1) he0 = relu(cat(x[src], x[tgt], edge_attr) @ W_n2e + b)
    mma_gemm<3><<<(N_EDGES + 127) / 128, 256>>>(
        N_EDGES, x, src, x, tgt, eattr, p_w + 0 * 65536,
        b_n2e, nullptr, nullptr, nullptr, p_he0);

    // 2) agg[btgt] += he0[bsrc] * bond_attr
    scatter_bond<<<(N_BONDS * H) / 256, 256>>>(bsrc, btgt, battr);

    // 3) he = relu(cat(he0, agg) @ Wc1 + b)
    mma_gemm<2><<<(N_EDGES + 127) / 128, 256>>>(
        N_EDGES, p_he0, nullptr, p_agg, nullptr, nullptr, p_w + 3 * 65536,
        Wc1b, nullptr, nullptr, nullptr, out_he);

    // 4) ha = battr + relu(he0[bsrc]@A1 + he0[btgt]@A2 + battr@A3 + biases)
    mma_gemm<3><<<(N_BONDS + 127) / 128, 256>>>(
        N_BONDS, p_he0, bsrc, p_he0, btgt, battr, p_w + 5 * 65536,
        A1b, A2b, A3b, battr, out_ha);

    // 5-7) attention
    attn_beta<<<(N_EDGES * 32) / 256, 256>>>(x, src, tgt, out_he, attnw, attnb);
    attn_den<<<(N_EDGES * NH + 255) / 256, 256>>>(tgt);
    attn_scatter<<<(N_EDGES * H) / 256, 256>>>(x, src, tgt, out_he);

    // 8) hx = relu(cat(x, agg2) @ Wc2 + b)
    mma_gemm<2><<<(N_NODES + 127) / 128, 256>>>(
        N_NODES, x, nullptr, p_agg2, nullptr, nullptr, p_w + 8 * 65536,
        Wc2b, nullptr, nullptr, nullptr, out_hx);
}

// round 6
// speedup vs baseline: 2.1585x; 1.1898x over previous
#include <cuda_runtime.h>
#include <cuda_bf16.h>
#include <math.h>
#include <stdint.h>

#define N_NODES 50000
#define N_EDGES 600000
#define N_BONDS 600000
#define H 128
#define NH 8

// ---------------- scratch ----------------
__device__ float    g_he0 [(size_t)N_EDGES * H];
__device__ float    g_agg [(size_t)N_EDGES * H];
__device__ float    g_agg2[(size_t)N_NODES * H];
__device__ float    g_beta[(size_t)N_EDGES * NH];
__device__ float    g_ex  [(size_t)N_EDGES * NH];
__device__ float    g_den [(size_t)N_NODES * NH];
__device__ unsigned g_nmax[(size_t)N_NODES * NH];
// 10 weight 128x128 K-slices, each stored transposed [n][k] bf16: [hi 32KB][lo 32KB]
__device__ unsigned char g_wsplit[10 * 2 * 32768];

__device__ __forceinline__ unsigned fflip(float f) {
    unsigned u = __float_as_uint(f);
    return (u & 0x80000000u) ? ~u : (u | 0x80000000u);
}
__device__ __forceinline__ float funflip(unsigned u) {
    return __uint_as_float((u & 0x80000000u) ? (u ^ 0x80000000u) : ~u);
}
__device__ __forceinline__ void split_bf16(float v, unsigned short& hi, unsigned short& lo) {
    __nv_bfloat16 h = __float2bfloat16_rn(v);
    float r = v - __bfloat162float(h);
    __nv_bfloat16 l = __float2bfloat16_rn(r);
    hi = __bfloat16_as_ushort(h);
    lo = __bfloat16_as_ushort(l);
}
__device__ __forceinline__ uint32_t smem_u32(const void* p) {
    uint32_t a;
    asm("{ .reg .u64 t; cvta.to.shared.u64 t, %1; cvt.u32.u64 %0, t; }" : "=r"(a) : "l"(p));
    return a;
}
__device__ __forceinline__ void mma_bf16(float* d, const unsigned* a, unsigned b0, unsigned b1) {
    asm volatile(
        "mma.sync.aligned.m16n8k16.row.col.f32.bf16.bf16.f32 "
        "{%0,%1,%2,%3}, {%4,%5,%6,%7}, {%8,%9}, {%0,%1,%2,%3};"
        : "+f"(d[0]), "+f"(d[1]), "+f"(d[2]), "+f"(d[3])
        : "r"(a[0]), "r"(a[1]), "r"(a[2]), "r"(a[3]), "r"(b0), "r"(b1));
}
__device__ __forceinline__ void ldmx4(unsigned& r0, unsigned& r1, unsigned& r2, unsigned& r3,
                                      uint32_t addr) {
    asm volatile("ldmatrix.sync.aligned.m8n8.x4.shared.b16 {%0,%1,%2,%3}, [%4];"
                 : "=r"(r0), "=r"(r1), "=r"(r2), "=r"(r3) : "r"(addr));
}

__global__ __launch_bounds__(256) void zero_scratch() {
    size_t idx = (size_t)blockIdx.x * 256 + threadIdx.x;
    if (idx < (size_t)N_EDGES * H) g_agg[idx] = 0.f;
    if (idx < (size_t)N_NODES * H) g_agg2[idx] = 0.f;
    if (idx < (size_t)N_NODES * NH) { g_den[idx] = 0.f; g_nmax[idx] = 0x007FFFFFu; }
}

// ---------------- weight prep: fp32 W[128k][128n] slice -> transposed bf16 hi/lo [n][k] ----------------
__global__ __launch_bounds__(256) void prep_wslice(
    const float* __restrict__ W, unsigned short* __restrict__ dsthi, unsigned short* __restrict__ dstlo)
{
    int e = blockIdx.x * 256 + threadIdx.x;
    int k = e >> 7;
    int n = e & 127;
    float v = W[k * 128 + n];
    unsigned short h, l;
    split_bf16(v, h, l);
    dsthi[n * 128 + k] = h;
    dstlo[n * 128 + k] = l;
}

// ==================================================================================
// split-bf16 HMMA GEMM v2: BM=128, BN=128, BK=32, 256 thr, ldmatrix + double buffer
// smem (dynamic): A tiles [2 stage][2 hl][128][40] ushort, then B same. 80 KB.
// ==================================================================================
#define SROW 40                       // ushort row stride (80 B = 20 words, ldmatrix conflict-free)
#define PLANE (128 * SROW)            // ushorts per plane
#define SMEM_GEMM_BYTES (2 * 2 * PLANE * 2 * 2)   // A + B regions, bytes

template<int NSEG>
__global__ __launch_bounds__(256, 1)
void mma_gemm(
    int M,
    const float* __restrict__ S0, const int* __restrict__ I0,
    const float* __restrict__ S1, const int* __restrict__ I1,
    const float* __restrict__ S2,
    const unsigned char* __restrict__ wsl,
    const float* __restrict__ B0, const float* __restrict__ B1, const float* __restrict__ B2,
    const float* __restrict__ residual,
    float* __restrict__ out)
{
    extern __shared__ __align__(16) unsigned short smem[];
    unsigned short* sA = smem;                 // [stage][hl][row][SROW]
    unsigned short* sB = smem + 2 * 2 * PLANE; // [stage][hl][n][SROW]
    __shared__ int sI0[128], sI1[128];
    __shared__ float sbias[128];

    const int t = threadIdx.x;
    const int lane = t & 31;
    const int wid = t >> 5;
    const int warp_m = wid & 3;
    const int warp_n = wid >> 2;
    const int blockRow = blockIdx.x * 128;

    if (t < 128) {
        int r = blockRow + t;
        if (r >= M) r = M - 1;
        sI0[t] = I0 ? I0[r] : r;
        sI1[t] = I1 ? I1[r] : r;
        float b = B0[t];
        if (B1) b += B1[t];
        if (B2) b += B2[t];
        sbias[t] = b;
    }
    __syncthreads();

    // loader roles
    const int arow = t >> 1;
    const int aseg = t & 1;                    // which 16-float half of the 32-k chunk
    const int arow_cl = (blockRow + arow < M) ? (blockRow + arow) : (M - 1);
    const int bh = t >> 7;                     // hi/lo plane
    const int bn = t & 127;                    // B row (n)

    const uint32_t sa_u32 = smem_u32(sA);
    const uint32_t sb_u32 = smem_u32(sB);

    float d[2][8][4];
#pragma unroll
    for (int mt = 0; mt < 2; ++mt)
#pragma unroll
        for (int nt = 0; nt < 8; ++nt)
#pragma unroll
            for (int c = 0; c < 4; ++c) d[mt][nt][c] = 0.f;

    const int NITER = NSEG * 4;

    float pfA[16];
    uint4 pfB[4];

    // ---- prefetch helpers (inline) ----
#define LOAD_GL(kt_) do { \
        int s_ = (kt_) >> 2; \
        const float* rp_; \
        if (s_ == 0)      rp_ = S0 + (size_t)sI0[arow] * H; \
        else if (s_ == 1) rp_ = S1 + (size_t)sI1[arow] * H; \
        else              rp_ = S2 + (size_t)arow_cl * H; \
        int kloc_ = ((kt_) & 3) * 32 + aseg * 16; \
        _Pragma("unroll") \
        for (int i_ = 0; i_ < 4; ++i_) { \
            float4 v_ = *(const float4*)(rp_ + kloc_ + i_ * 4); \
            pfA[i_ * 4 + 0] = v_.x; pfA[i_ * 4 + 1] = v_.y; \
            pfA[i_ * 4 + 2] = v_.z; pfA[i_ * 4 + 3] = v_.w; \
        } \
        const unsigned char* src_ = wsl + (size_t)s_ * 65536 + (size_t)bh * 32768 \
                                  + (size_t)bn * 256 + (size_t)((kt_) & 3) * 64; \
        pfB[0] = *(const uint4*)(src_); \
        pfB[1] = *(const uint4*)(src_ + 16); \
        pfB[2] = *(const uint4*)(src_ + 32); \
        pfB[3] = *(const uint4*)(src_ + 48); \
    } while (0)

#define STORE_SM(stage_) do { \
        unsigned uh_[8], ul_[8]; \
        _Pragma("unroll") \
        for (int i_ = 0; i_ < 8; ++i_) { \
            unsigned short h0_, l0_, h1_, l1_; \
            split_bf16(pfA[2 * i_], h0_, l0_); \
            split_bf16(pfA[2 * i_ + 1], h1_, l1_); \
            uh_[i_] = (unsigned)h0_ | ((unsigned)h1_ << 16); \
            ul_[i_] = (unsigned)l0_ | ((unsigned)l1_ << 16); \
        } \
        unsigned short* ah_ = sA + (size_t)(stage_) * 2 * PLANE + (size_t)arow * SROW + aseg * 16; \
        unsigned short* al_ = ah_ + PLANE; \
        *(uint4*)(ah_)     = make_uint4(uh_[0], uh_[1], uh_[2], uh_[3]); \
        *(uint4*)(ah_ + 8) = make_uint4(uh_[4], uh_[5], uh_[6], uh_[7]); \
        *(uint4*)(al_)     = make_uint4(ul_[0], ul_[1], ul_[2], ul_[3]); \
        *(uint4*)(al_ + 8) = make_uint4(ul_[4], ul_[5], ul_[6], ul_[7]); \
        unsigned short* bp_ = sB + (size_t)(stage_) * 2 * PLANE + (size_t)bh * PLANE + (size_t)bn * SROW; \
        *(uint4*)(bp_)      = pfB[0]; \
        *(uint4*)(bp_ + 8)  = pfB[1]; \
        *(uint4*)(bp_ + 16) = pfB[2]; \
        *(uint4*)(bp_ + 24) = pfB[3]; \
    } while (0)

    LOAD_GL(0);
    STORE_SM(0);
    __syncthreads();

    for (int kt = 0; kt < NITER; ++kt) {
        const int stage = kt & 1;
        if (kt + 1 < NITER) LOAD_GL(kt + 1);

        // ---- MMAs from stage ----
        const uint32_t aplane = sa_u32 + (uint32_t)stage * 2 * PLANE * 2;   // bytes
        const uint32_t bplane = sb_u32 + (uint32_t)stage * 2 * PLANE * 2;
        const uint32_t lrow = (lane & 15);
        const uint32_t lcol = (lane >> 4) * 8;

#pragma unroll
        for (int ks = 0; ks < 2; ++ks) {
            // A fragments: [hl][mt][4]
            unsigned af[2][2][4];
#pragma unroll
            for (int hl = 0; hl < 2; ++hl)
#pragma unroll
                for (int mt = 0; mt < 2; ++mt) {
                    uint32_t row = warp_m * 32 + mt * 16 + lrow;
                    uint32_t addr = aplane + (uint32_t)hl * PLANE * 2
                                  + (row * SROW + ks * 16 + lcol) * 2;
                    ldmx4(af[hl][mt][0], af[hl][mt][1], af[hl][mt][2], af[hl][mt][3], addr);
                }
            // B fragments: [hl][nt][2]
            unsigned bf[2][8][2];
#pragma unroll
            for (int hl = 0; hl < 2; ++hl)
#pragma unroll
                for (int pr = 0; pr < 4; ++pr) {
                    uint32_t row = warp_n * 64 + pr * 16 + lrow;
                    uint32_t addr = bplane + (uint32_t)hl * PLANE * 2
                                  + (row * SROW + ks * 16 + lcol) * 2;
                    unsigned r0, r1, r2, r3;
                    ldmx4(r0, r1, r2, r3, addr);
                    bf[hl][pr * 2][0] = r0;  bf[hl][pr * 2][1] = r2;
                    bf[hl][pr * 2 + 1][0] = r1;  bf[hl][pr * 2 + 1][1] = r3;
                }
#pragma unroll
            for (int nt = 0; nt < 8; ++nt)
#pragma unroll
                for (int mt = 0; mt < 2; ++mt) {
                    mma_bf16(d[mt][nt], af[0][mt], bf[0][nt][0], bf[0][nt][1]);
                    mma_bf16(d[mt][nt], af[1][mt], bf[0][nt][0], bf[0][nt][1]);
                    mma_bf16(d[mt][nt], af[0][mt], bf[1][nt][0], bf[1][nt][1]);
                }
        }

        if (kt + 1 < NITER) {
            STORE_SM((kt + 1) & 1);
            __syncthreads();
        }
    }
#undef LOAD_GL
#undef STORE_SM

    // ---- epilogue ----
#pragma unroll
    for (int mt = 0; mt < 2; ++mt) {
#pragma unroll
        for (int half = 0; half < 2; ++half) {
            int r = warp_m * 32 + mt * 16 + (lane >> 2) + half * 8;
            int grow = blockRow + r;
            if (grow >= M) continue;
#pragma unroll
            for (int nt = 0; nt < 8; ++nt) {
                int gc = warp_n * 64 + nt * 8 + (lane & 3) * 2;
                float v0 = d[mt][nt][half * 2 + 0] + sbias[gc];
                float v1 = d[mt][nt][half * 2 + 1] + sbias[gc + 1];
                v0 = fmaxf(v0, 0.f);
                v1 = fmaxf(v1, 0.f);
                if (residual) {
                    float2 rr = *(const float2*)(residual + (size_t)grow * H + gc);
                    v0 += rr.x;
                    v1 += rr.y;
                }
                *(float2*)(out + (size_t)grow * H + gc) = make_float2(v0, v1);
            }
        }
    }
}

// ---------------- bond scatter ----------------
__global__ __launch_bounds__(256) void scatter_bond(
    const int* __restrict__ bsrc, const int* __restrict__ btgt,
    const float* __restrict__ battr)
{
    size_t idx = (size_t)blockIdx.x * 256 + threadIdx.x;
    int b = (int)(idx >> 7);
    int c = (int)(idx & 127);
    int s = bsrc[b];
    int g = btgt[b];
    atomicAdd(&g_agg[(size_t)g * H + c], g_he0[(size_t)s * H + c] * battr[idx]);
}

// ---------------- attention pass 1 ----------------
__global__ __launch_bounds__(256) void attn_beta(
    const float* __restrict__ x,
    const int* __restrict__ src, const int* __restrict__ tgt,
    const float* __restrict__ he,
    const float* __restrict__ attnw, const float* __restrict__ attnb)
{
    int gt = blockIdx.x * 256 + threadIdx.x;
    int e = gt >> 5;
    int lane = gt & 31;
    int s = src[e];
    int g = tgt[e];
    int c = lane * 4;
    int d = c & 15;
    float4 xs = *(const float4*)(x + (size_t)s * H + c);
    float4 hh = *(const float4*)(he + (size_t)e * H + c);
    float4 xt = *(const float4*)(x + (size_t)g * H + c);
    float p = xs.x * hh.x * attnw[d]     + xt.x * attnw[16 + d]
            + xs.y * hh.y * attnw[d + 1] + xt.y * attnw[17 + d]
            + xs.z * hh.z * attnw[d + 2] + xt.z * attnw[18 + d]
            + xs.w * hh.w * attnw[d + 3] + xt.w * attnw[19 + d];
    p += __shfl_xor_sync(0xffffffffu, p, 1);
    p += __shfl_xor_sync(0xffffffffu, p, 2);
    if ((lane & 3) == 0) {
        int h = lane >> 2;
        float b = p + attnb[0];
        b = (b > 0.f) ? b : 0.01f * b;
        g_beta[(size_t)e * NH + h] = b;
        atomicMax(&g_nmax[(size_t)g * NH + h], fflip(b));
    }
}

// ---------------- attention pass 2 ----------------
__global__ __launch_bounds__(256) void attn_den(const int* __restrict__ tgt)
{
    int idx = blockIdx.x * 256 + threadIdx.x;
    if (idx >= N_EDGES * NH) return;
    int e = idx >> 3;
    int h = idx & 7;
    int g = tgt[e];
    float m = funflip(g_nmax[(size_t)g * NH + h]);
    float ex = expf(g_beta[idx] - m);
    g_ex[idx] = ex;
    atomicAdd(&g_den[(size_t)g * NH + h], ex);
}

// ---------------- attention pass 3 ----------------
__global__ __launch_bounds__(256) void attn_scatter(
    const float* __restrict__ x,
    const int* __restrict__ src, const int* __restrict__ tgt,
    const float* __restrict__ he)
{
    size_t idx = (size_t)blockIdx.x * 256 + threadIdx.x;
    int e = (int)(idx >> 7);
    int c = (int)(idx & 127);
    int h = c >> 4;
    int s = src[e];
    int g = tgt[e];
    float alpha = g_ex[(size_t)e * NH + h] / (g_den[(size_t)g * NH + h] + 1e-16f);
    float val = alpha * x[(size_t)s * H + c] * he[idx];
    atomicAdd(&g_agg2[(size_t)g * H + c], val);
}

// ---------------- launch ----------------
extern "C" void kernel_launch(void* const* d_in, const int* in_sizes, int n_in,
                              void* d_out, int out_size)
{
    const float* x     = (const float*)d_in[0];
    const int*   ei    = (const int*)d_in[1];
    const float* eattr = (const float*)d_in[2];
    const int*   bei   = (const int*)d_in[3];
    const float* battr = (const float*)d_in[4];
    const float* W_n2e = (const float*)d_in[5];
    const float* b_n2e = (const float*)d_in[6];
    const float* A1w   = (const float*)d_in[7];
    const float* A1b   = (const float*)d_in[8];
    const float* A2w   = (const float*)d_in[9];
    const float* A2b   = (const float*)d_in[10];
    const float* A3w   = (const float*)d_in[11];
    const float* A3b   = (const float*)d_in[12];
    const float* Wc1w  = (const float*)d_in[13];
    const float* Wc1b  = (const float*)d_in[14];
    const float* attnw = (const float*)d_in[15];
    const float* attnb = (const float*)d_in[16];
    const float* Wc2w  = (const float*)d_in[17];
    const float* Wc2b  = (const float*)d_in[18];

    float* out    = (float*)d_out;
    float* out_hx = out;
    float* out_he = out + (size_t)N_NODES * H;
    float* out_ha = out_he + (size_t)N_EDGES * H;

    const int* src  = ei;
    const int* tgt  = ei + N_EDGES;
    const int* bsrc = bei;
    const int* btgt = bei + N_BONDS;

    float *p_he0, *p_agg, *p_agg2;
    unsigned char* p_w;
    cudaGetSymbolAddress((void**)&p_he0,  g_he0);
    cudaGetSymbolAddress((void**)&p_agg,  g_agg);
    cudaGetSymbolAddress((void**)&p_agg2, g_agg2);
    cudaGetSymbolAddress((void**)&p_w,    g_wsplit);

    cudaFuncSetAttribute(mma_gemm<2>, cudaFuncAttributeMaxDynamicSharedMemorySize, SMEM_GEMM_BYTES);
    cudaFuncSetAttribute(mma_gemm<3>, cudaFuncAttributeMaxDynamicSharedMemorySize, SMEM_GEMM_BYTES);

    // weight slice table: [0..2]=W_n2e, [3..4]=Wc1, [5]=A1, [6]=A2, [7]=A3, [8..9]=Wc2
    const float* wsrc[10] = {
        W_n2e, W_n2e + 128 * H, W_n2e + 256 * H,
        Wc1w, Wc1w + 128 * H,
        A1w, A2w, A3w,
        Wc2w, Wc2w + 128 * H
    };
    for (int i = 0; i < 10; ++i)
        prep_wslice<<<64, 256>>>(wsrc[i],
            (unsigned short*)(p_w + (size_t)i * 65536),
            (unsigned short*)(p_w + (size_t)i * 65536 + 32768));

    zero_scratch<<<(N_EDGES * H) / 256, 256>>>();

    // 1) he0 = relu(cat(x[src], x[tgt], edge_attr) @ W_n2e + b)
    mma_gemm<3><<<(N_EDGES + 127) / 128, 256, SMEM_GEMM_BYTES>>>(
        N_EDGES, x, src, x, tgt, eattr, p_w + 0 * 65536,
        b_n2e, nullptr, nullptr, nullptr, p_he0);

    // 2) agg[btgt] += he0[bsrc] * bond_attr
    scatter_bond<<<(N_BONDS * H) / 256, 256>>>(bsrc, btgt, battr);

    // 3) he = relu(cat(he0, agg) @ Wc1 + b)
    mma_gemm<2><<<(N_EDGES + 127) / 128, 256, SMEM_GEMM_BYTES>>>(
        N_EDGES, p_he0, nullptr, p_agg, nullptr, nullptr, p_w + 3 * 65536,
        Wc1b, nullptr, nullptr, nullptr, out_he);

    // 4) ha = battr + relu(he0[bsrc]@A1 + he0[btgt]@A2 + battr@A3 + biases)
    mma_gemm<3><<<(N_BONDS + 127) / 128, 256, SMEM_GEMM_BYTES>>>(
        N_BONDS, p_he0, bsrc, p_he0, btgt, battr, p_w + 5 * 65536,
        A1b, A2b, A3b, battr, out_ha);

    // 5-7) attention
    attn_beta<<<(N_EDGES * 32) / 256, 256>>>(x, src, tgt, out_he, attnw, attnb);
    attn_den<<<(N_EDGES * NH + 255) / 256, 256>>>(tgt);
    attn_scatter<<<(N_EDGES * H) / 256, 256>>>(x, src, tgt, out_he);

    // 8) hx = relu(cat(x, agg2) @ Wc2 + b)
    mma_gemm<2><<<(N_NODES + 127) / 128, 256, SMEM_GEMM_BYTES>>>(
        N_NODES, x, nullptr, p_agg2, nullptr, nullptr, p_w + 8 * 65536,
        Wc2b, nullptr, nullptr, nullptr, out_hx);
}

// round 7
// speedup vs baseline: 2.3903x; 1.1074x over previous
#include <cuda_runtime.h>
#include <cuda_bf16.h>
#include <math.h>
#include <stdint.h>

#define N_NODES 50000
#define N_EDGES 600000
#define N_BONDS 600000
#define H 128
#define NH 8

// ---------------- scratch ----------------
__device__ float    g_he0 [(size_t)N_EDGES * H];
__device__ float    g_agg [(size_t)N_EDGES * H];
__device__ float    g_agg2[(size_t)N_NODES * H];
__device__ float    g_beta[(size_t)N_EDGES * NH];
__device__ float    g_ex  [(size_t)N_EDGES * NH];
__device__ float    g_den [(size_t)N_NODES * NH];
__device__ unsigned g_nmax[(size_t)N_NODES * NH];
// 10 weight 128x128 K-slices, each stored transposed [n][k] bf16: [hi 32KB][lo 32KB]
__device__ unsigned char g_wsplit[10 * 2 * 32768];

__device__ __forceinline__ unsigned fflip(float f) {
    unsigned u = __float_as_uint(f);
    return (u & 0x80000000u) ? ~u : (u | 0x80000000u);
}
__device__ __forceinline__ float funflip(unsigned u) {
    return __uint_as_float((u & 0x80000000u) ? (u ^ 0x80000000u) : ~u);
}
__device__ __forceinline__ void split_bf16(float v, unsigned short& hi, unsigned short& lo) {
    __nv_bfloat16 h = __float2bfloat16_rn(v);
    float r = v - __bfloat162float(h);
    __nv_bfloat16 l = __float2bfloat16_rn(r);
    hi = __bfloat16_as_ushort(h);
    lo = __bfloat16_as_ushort(l);
}
__device__ __forceinline__ uint32_t smem_u32(const void* p) {
    uint32_t a;
    asm("{ .reg .u64 t; cvta.to.shared.u64 t, %1; cvt.u32.u64 %0, t; }" : "=r"(a) : "l"(p));
    return a;
}
__device__ __forceinline__ void mma_bf16(float* d, const unsigned* a, unsigned b0, unsigned b1) {
    asm volatile(
        "mma.sync.aligned.m16n8k16.row.col.f32.bf16.bf16.f32 "
        "{%0,%1,%2,%3}, {%4,%5,%6,%7}, {%8,%9}, {%0,%1,%2,%3};"
        : "+f"(d[0]), "+f"(d[1]), "+f"(d[2]), "+f"(d[3])
        : "r"(a[0]), "r"(a[1]), "r"(a[2]), "r"(a[3]), "r"(b0), "r"(b1));
}
__device__ __forceinline__ void ldmx4(unsigned& r0, unsigned& r1, unsigned& r2, unsigned& r3,
                                      uint32_t addr) {
    asm volatile("ldmatrix.sync.aligned.m8n8.x4.shared.b16 {%0,%1,%2,%3}, [%4];"
                 : "=r"(r0), "=r"(r1), "=r"(r2), "=r"(r3) : "r"(addr));
}

__global__ __launch_bounds__(256) void zero_scratch() {
    size_t idx = (size_t)blockIdx.x * 256 + threadIdx.x;
    if (idx < (size_t)N_EDGES * H) g_agg[idx] = 0.f;
    if (idx < (size_t)N_NODES * H) g_agg2[idx] = 0.f;
    if (idx < (size_t)N_NODES * NH) { g_den[idx] = 0.f; g_nmax[idx] = 0x007FFFFFu; }
}

// ---------------- weight prep (all 10 slices in one launch) ----------------
struct WSrcs { const float* p[10]; };

__global__ __launch_bounds__(256) void prep_all(WSrcs ws, unsigned char* dst)
{
    int slice = blockIdx.x >> 6;                   // 64 blocks per slice
    int e = (blockIdx.x & 63) * 256 + threadIdx.x; // 0..16383
    int k = e >> 7;
    int n = e & 127;
    float v = ws.p[slice][k * 128 + n];
    unsigned short h, l;
    split_bf16(v, h, l);
    unsigned short* dsthi = (unsigned short*)(dst + (size_t)slice * 65536);
    unsigned short* dstlo = (unsigned short*)(dst + (size_t)slice * 65536 + 32768);
    dsthi[n * 128 + k] = h;
    dstlo[n * 128 + k] = l;
}

// ==================================================================================
// split-bf16 HMMA GEMM: BM=128, BN=128, BK=32, 256 thr, ldmatrix + double buffer
// ==================================================================================
#define SROW 40
#define PLANE (128 * SROW)
#define SMEM_GEMM_BYTES (2 * 2 * PLANE * 2 * 2)

template<int NSEG>
__global__ __launch_bounds__(256, 1)
void mma_gemm(
    int M,
    const float* __restrict__ S0, const int* __restrict__ I0,
    const float* __restrict__ S1, const int* __restrict__ I1,
    const float* __restrict__ S2,
    const unsigned char* __restrict__ wsl,
    const float* __restrict__ B0, const float* __restrict__ B1, const float* __restrict__ B2,
    const float* __restrict__ residual,
    float* __restrict__ out)
{
    extern __shared__ __align__(16) unsigned short smem[];
    unsigned short* sA = smem;
    unsigned short* sB = smem + 2 * 2 * PLANE;
    __shared__ int sI0[128], sI1[128];
    __shared__ float sbias[128];

    const int t = threadIdx.x;
    const int lane = t & 31;
    const int wid = t >> 5;
    const int warp_m = wid & 3;
    const int warp_n = wid >> 2;
    const int blockRow = blockIdx.x * 128;

    if (t < 128) {
        int r = blockRow + t;
        if (r >= M) r = M - 1;
        sI0[t] = I0 ? I0[r] : r;
        sI1[t] = I1 ? I1[r] : r;
        float b = B0[t];
        if (B1) b += B1[t];
        if (B2) b += B2[t];
        sbias[t] = b;
    }
    __syncthreads();

    const int arow = t >> 1;
    const int aseg = t & 1;
    const int arow_cl = (blockRow + arow < M) ? (blockRow + arow) : (M - 1);
    const int bh = t >> 7;
    const int bn = t & 127;

    const uint32_t sa_u32 = smem_u32(sA);
    const uint32_t sb_u32 = smem_u32(sB);

    float d[2][8][4];
#pragma unroll
    for (int mt = 0; mt < 2; ++mt)
#pragma unroll
        for (int nt = 0; nt < 8; ++nt)
#pragma unroll
            for (int c = 0; c < 4; ++c) d[mt][nt][c] = 0.f;

    const int NITER = NSEG * 4;

    float pfA[16];
    uint4 pfB[4];

#define LOAD_GL(kt_) do { \
        int s_ = (kt_) >> 2; \
        const float* rp_; \
        if (s_ == 0)      rp_ = S0 + (size_t)sI0[arow] * H; \
        else if (s_ == 1) rp_ = S1 + (size_t)sI1[arow] * H; \
        else              rp_ = S2 + (size_t)arow_cl * H; \
        int kloc_ = ((kt_) & 3) * 32 + aseg * 16; \
        _Pragma("unroll") \
        for (int i_ = 0; i_ < 4; ++i_) { \
            float4 v_ = *(const float4*)(rp_ + kloc_ + i_ * 4); \
            pfA[i_ * 4 + 0] = v_.x; pfA[i_ * 4 + 1] = v_.y; \
            pfA[i_ * 4 + 2] = v_.z; pfA[i_ * 4 + 3] = v_.w; \
        } \
        const unsigned char* src_ = wsl + (size_t)s_ * 65536 + (size_t)bh * 32768 \
                                  + (size_t)bn * 256 + (size_t)((kt_) & 3) * 64; \
        pfB[0] = *(const uint4*)(src_); \
        pfB[1] = *(const uint4*)(src_ + 16); \
        pfB[2] = *(const uint4*)(src_ + 32); \
        pfB[3] = *(const uint4*)(src_ + 48); \
    } while (0)

#define STORE_SM(stage_) do { \
        unsigned uh_[8], ul_[8]; \
        _Pragma("unroll") \
        for (int i_ = 0; i_ < 8; ++i_) { \
            unsigned short h0_, l0_, h1_, l1_; \
            split_bf16(pfA[2 * i_], h0_, l0_); \
            split_bf16(pfA[2 * i_ + 1], h1_, l1_); \
            uh_[i_] = (unsigned)h0_ | ((unsigned)h1_ << 16); \
            ul_[i_] = (unsigned)l0_ | ((unsigned)l1_ << 16); \
        } \
        unsigned short* ah_ = sA + (size_t)(stage_) * 2 * PLANE + (size_t)arow * SROW + aseg * 16; \
        unsigned short* al_ = ah_ + PLANE; \
        *(uint4*)(ah_)     = make_uint4(uh_[0], uh_[1], uh_[2], uh_[3]); \
        *(uint4*)(ah_ + 8) = make_uint4(uh_[4], uh_[5], uh_[6], uh_[7]); \
        *(uint4*)(al_)     = make_uint4(ul_[0], ul_[1], ul_[2], ul_[3]); \
        *(uint4*)(al_ + 8) = make_uint4(ul_[4], ul_[5], ul_[6], ul_[7]); \
        unsigned short* bp_ = sB + (size_t)(stage_) * 2 * PLANE + (size_t)bh * PLANE + (size_t)bn * SROW; \
        *(uint4*)(bp_)      = pfB[0]; \
        *(uint4*)(bp_ + 8)  = pfB[1]; \
        *(uint4*)(bp_ + 16) = pfB[2]; \
        *(uint4*)(bp_ + 24) = pfB[3]; \
    } while (0)

    LOAD_GL(0);
    STORE_SM(0);
    __syncthreads();

    for (int kt = 0; kt < NITER; ++kt) {
        const int stage = kt & 1;
        if (kt + 1 < NITER) LOAD_GL(kt + 1);

        const uint32_t aplane = sa_u32 + (uint32_t)stage * 2 * PLANE * 2;
        const uint32_t bplane = sb_u32 + (uint32_t)stage * 2 * PLANE * 2;
        const uint32_t lrow = (lane & 15);
        const uint32_t lcol = (lane >> 4) * 8;

#pragma unroll
        for (int ks = 0; ks < 2; ++ks) {
            unsigned af[2][2][4];
#pragma unroll
            for (int hl = 0; hl < 2; ++hl)
#pragma unroll
                for (int mt = 0; mt < 2; ++mt) {
                    uint32_t row = warp_m * 32 + mt * 16 + lrow;
                    uint32_t addr = aplane + (uint32_t)hl * PLANE * 2
                                  + (row * SROW + ks * 16 + lcol) * 2;
                    ldmx4(af[hl][mt][0], af[hl][mt][1], af[hl][mt][2], af[hl][mt][3], addr);
                }
            unsigned bf[2][8][2];
#pragma unroll
            for (int hl = 0; hl < 2; ++hl)
#pragma unroll
                for (int pr = 0; pr < 4; ++pr) {
                    uint32_t row = warp_n * 64 + pr * 16 + lrow;
                    uint32_t addr = bplane + (uint32_t)hl * PLANE * 2
                                  + (row * SROW + ks * 16 + lcol) * 2;
                    unsigned r0, r1, r2, r3;
                    ldmx4(r0, r1, r2, r3, addr);
                    bf[hl][pr * 2][0] = r0;  bf[hl][pr * 2][1] = r2;
                    bf[hl][pr * 2 + 1][0] = r1;  bf[hl][pr * 2 + 1][1] = r3;
                }
#pragma unroll
            for (int nt = 0; nt < 8; ++nt)
#pragma unroll
                for (int mt = 0; mt < 2; ++mt) {
                    mma_bf16(d[mt][nt], af[0][mt], bf[0][nt][0], bf[0][nt][1]);
                    mma_bf16(d[mt][nt], af[1][mt], bf[0][nt][0], bf[0][nt][1]);
                    mma_bf16(d[mt][nt], af[0][mt], bf[1][nt][0], bf[1][nt][1]);
                }
        }

        if (kt + 1 < NITER) {
            STORE_SM((kt + 1) & 1);
            __syncthreads();
        }
    }
#undef LOAD_GL
#undef STORE_SM

#pragma unroll
    for (int mt = 0; mt < 2; ++mt) {
#pragma unroll
        for (int half = 0; half < 2; ++half) {
            int r = warp_m * 32 + mt * 16 + (lane >> 2) + half * 8;
            int grow = blockRow + r;
            if (grow >= M) continue;
#pragma unroll
            for (int nt = 0; nt < 8; ++nt) {
                int gc = warp_n * 64 + nt * 8 + (lane & 3) * 2;
                float v0 = d[mt][nt][half * 2 + 0] + sbias[gc];
                float v1 = d[mt][nt][half * 2 + 1] + sbias[gc + 1];
                v0 = fmaxf(v0, 0.f);
                v1 = fmaxf(v1, 0.f);
                if (residual) {
                    float2 rr = *(const float2*)(residual + (size_t)grow * H + gc);
                    v0 += rr.x;
                    v1 += rr.y;
                }
                *(float2*)(out + (size_t)grow * H + gc) = make_float2(v0, v1);
            }
        }
    }
}

// ---------------- bond scatter (float4 per thread) ----------------
__global__ __launch_bounds__(256) void scatter_bond(
    const int* __restrict__ bsrc, const int* __restrict__ btgt,
    const float* __restrict__ battr)
{
    size_t idx = (size_t)blockIdx.x * 256 + threadIdx.x;   // over N_BONDS*32
    int b = (int)(idx >> 5);
    int c = (int)(idx & 31) * 4;
    int s = bsrc[b];
    int g = btgt[b];
    float4 hv = *(const float4*)(g_he0 + (size_t)s * H + c);
    float4 bv = *(const float4*)(battr + (size_t)b * H + c);
    float* dst = g_agg + (size_t)g * H + c;
    atomicAdd(dst + 0, hv.x * bv.x);
    atomicAdd(dst + 1, hv.y * bv.y);
    atomicAdd(dst + 2, hv.z * bv.z);
    atomicAdd(dst + 3, hv.w * bv.w);
}

// ---------------- attention pass 1 ----------------
__global__ __launch_bounds__(256) void attn_beta(
    const float* __restrict__ x,
    const int* __restrict__ src, const int* __restrict__ tgt,
    const float* __restrict__ he,
    const float* __restrict__ attnw, const float* __restrict__ attnb)
{
    int gt = blockIdx.x * 256 + threadIdx.x;
    int e = gt >> 5;
    int lane = gt & 31;
    int s = src[e];
    int g = tgt[e];
    int c = lane * 4;
    int d = c & 15;
    float4 xs = *(const float4*)(x + (size_t)s * H + c);
    float4 hh = *(const float4*)(he + (size_t)e * H + c);
    float4 xt = *(const float4*)(x + (size_t)g * H + c);
    float p = xs.x * hh.x * attnw[d]     + xt.x * attnw[16 + d]
            + xs.y * hh.y * attnw[d + 1] + xt.y * attnw[17 + d]
            + xs.z * hh.z * attnw[d + 2] + xt.z * attnw[18 + d]
            + xs.w * hh.w * attnw[d + 3] + xt.w * attnw[19 + d];
    p += __shfl_xor_sync(0xffffffffu, p, 1);
    p += __shfl_xor_sync(0xffffffffu, p, 2);
    if ((lane & 3) == 0) {
        int h = lane >> 2;
        float b = p + attnb[0];
        b = (b > 0.f) ? b : 0.01f * b;
        g_beta[(size_t)e * NH + h] = b;
        atomicMax(&g_nmax[(size_t)g * NH + h], fflip(b));
    }
}

// ---------------- attention pass 2 ----------------
__global__ __launch_bounds__(256) void attn_den(const int* __restrict__ tgt)
{
    int idx = blockIdx.x * 256 + threadIdx.x;
    if (idx >= N_EDGES * NH) return;
    int e = idx >> 3;
    int h = idx & 7;
    int g = tgt[e];
    float m = funflip(g_nmax[(size_t)g * NH + h]);
    float ex = expf(g_beta[idx] - m);
    g_ex[idx] = ex;
    atomicAdd(&g_den[(size_t)g * NH + h], ex);
}

// ---------------- attention pass 3 (float4 per thread) ----------------
__global__ __launch_bounds__(256) void attn_scatter(
    const float* __restrict__ x,
    const int* __restrict__ src, const int* __restrict__ tgt,
    const float* __restrict__ he)
{
    size_t idx = (size_t)blockIdx.x * 256 + threadIdx.x;   // over N_EDGES*32
    int e = (int)(idx >> 5);
    int c = (int)(idx & 31) * 4;
    int h = c >> 4;
    int s = src[e];
    int g = tgt[e];
    float alpha = g_ex[(size_t)e * NH + h] / (g_den[(size_t)g * NH + h] + 1e-16f);
    float4 xv = *(const float4*)(x + (size_t)s * H + c);
    float4 hv = *(const float4*)(he + (size_t)e * H + c);
    float* dst = g_agg2 + (size_t)g * H + c;
    atomicAdd(dst + 0, alpha * xv.x * hv.x);
    atomicAdd(dst + 1, alpha * xv.y * hv.y);
    atomicAdd(dst + 2, alpha * xv.z * hv.z);
    atomicAdd(dst + 3, alpha * xv.w * hv.w);
}

// ---------------- launch ----------------
extern "C" void kernel_launch(void* const* d_in, const int* in_sizes, int n_in,
                              void* d_out, int out_size)
{
    const float* x     = (const float*)d_in[0];
    const int*   ei    = (const int*)d_in[1];
    const float* eattr = (const float*)d_in[2];
    const int*   bei   = (const int*)d_in[3];
    const float* battr = (const float*)d_in[4];
    const float* W_n2e = (const float*)d_in[5];
    const float* b_n2e = (const float*)d_in[6];
    const float* A1w   = (const float*)d_in[7];
    const float* A1b   = (const float*)d_in[8];
    const float* A2w   = (const float*)d_in[9];
    const float* A2b   = (const float*)d_in[10];
    const float* A3w   = (const float*)d_in[11];
    const float* A3b   = (const float*)d_in[12];
    const float* Wc1w  = (const float*)d_in[13];
    const float* Wc1b  = (const float*)d_in[14];
    const float* attnw = (const float*)d_in[15];
    const float* attnb = (const float*)d_in[16];
    const float* Wc2w  = (const float*)d_in[17];
    const float* Wc2b  = (const float*)d_in[18];

    float* out    = (float*)d_out;
    float* out_hx = out;
    float* out_he = out + (size_t)N_NODES * H;
    float* out_ha = out_he + (size_t)N_EDGES * H;

    const int* src  = ei;
    const int* tgt  = ei + N_EDGES;
    const int* bsrc = bei;
    const int* btgt = bei + N_BONDS;

    float *p_he0, *p_agg, *p_agg2;
    unsigned char* p_w;
    cudaGetSymbolAddress((void**)&p_he0,  g_he0);
    cudaGetSymbolAddress((void**)&p_agg,  g_agg);
    cudaGetSymbolAddress((void**)&p_agg2, g_agg2);
    cudaGetSymbolAddress((void**)&p_w,    g_wsplit);

    static cudaStream_t s1 = nullptr;
    static cudaEvent_t evStart, evZ, evA, evB;
    if (!s1) {
        cudaStreamCreateWithFlags(&s1, cudaStreamNonBlocking);
        cudaEventCreateWithFlags(&evStart, cudaEventDisableTiming);
        cudaEventCreateWithFlags(&evZ, cudaEventDisableTiming);
        cudaEventCreateWithFlags(&evA, cudaEventDisableTiming);
        cudaEventCreateWithFlags(&evB, cudaEventDisableTiming);
        cudaFuncSetAttribute(mma_gemm<2>, cudaFuncAttributeMaxDynamicSharedMemorySize, SMEM_GEMM_BYTES);
        cudaFuncSetAttribute(mma_gemm<3>, cudaFuncAttributeMaxDynamicSharedMemorySize, SMEM_GEMM_BYTES);
    }

    // ---- weight prep (main stream) ----
    WSrcs ws;
    ws.p[0] = W_n2e; ws.p[1] = W_n2e + 128 * H; ws.p[2] = W_n2e + 256 * H;
    ws.p[3] = Wc1w;  ws.p[4] = Wc1w + 128 * H;
    ws.p[5] = A1w;   ws.p[6] = A2w;   ws.p[7] = A3w;
    ws.p[8] = Wc2w;  ws.p[9] = Wc2w + 128 * H;
    prep_all<<<640, 256>>>(ws, p_w);

    // fork side stream; zero_scratch runs concurrent with GEMM1
    cudaEventRecord(evStart, 0);
    cudaStreamWaitEvent(s1, evStart, 0);
    zero_scratch<<<(N_EDGES * H) / 256, 256, 0, s1>>>();
    cudaEventRecord(evZ, s1);

    // 1) he0 = relu(cat(x[src], x[tgt], edge_attr) @ W_n2e + b)   [main]
    mma_gemm<3><<<(N_EDGES + 127) / 128, 256, SMEM_GEMM_BYTES>>>(
        N_EDGES, x, src, x, tgt, eattr, p_w + 0 * 65536,
        b_n2e, nullptr, nullptr, nullptr, p_he0);
    cudaEventRecord(evA, 0);

    // 4) ha GEMM on side stream, concurrent with scatter/he/attention
    cudaStreamWaitEvent(s1, evA, 0);
    mma_gemm<3><<<(N_BONDS + 127) / 128, 256, SMEM_GEMM_BYTES, s1>>>(
        N_BONDS, p_he0, bsrc, p_he0, btgt, battr, p_w + 5 * 65536,
        A1b, A2b, A3b, battr, out_ha);
    cudaEventRecord(evB, s1);

    // main chain: needs zeroed scratch before scatter/attention
    cudaStreamWaitEvent(0, evZ, 0);

    // 2) agg[btgt] += he0[bsrc] * bond_attr
    scatter_bond<<<(N_BONDS * 32) / 256, 256>>>(bsrc, btgt, battr);

    // 3) he = relu(cat(he0, agg) @ Wc1 + b)
    mma_gemm<2><<<(N_EDGES + 127) / 128, 256, SMEM_GEMM_BYTES>>>(
        N_EDGES, p_he0, nullptr, p_agg, nullptr, nullptr, p_w + 3 * 65536,
        Wc1b, nullptr, nullptr, nullptr, out_he);

    // 5-7) attention
    attn_beta<<<(N_EDGES * 32) / 256, 256>>>(x, src, tgt, out_he, attnw, attnb);
    attn_den<<<(N_EDGES * NH + 255) / 256, 256>>>(tgt);
    attn_scatter<<<(N_EDGES * 32) / 256, 256>>>(x, src, tgt, out_he);

    // 8) hx = relu(cat(x, agg2) @ Wc2 + b)
    mma_gemm<2><<<(N_NODES + 127) / 128, 256, SMEM_GEMM_BYTES>>>(
        N_NODES, x, nullptr, p_agg2, nullptr, nullptr, p_w + 8 * 65536,
        Wc2b, nullptr, nullptr, nullptr, out_hx);

    // join side branch
    cudaStreamWaitEvent(0, evB, 0);
}

// round 8
// speedup vs baseline: 2.7304x; 1.1423x over previous
#include <cuda_runtime.h>
#include <cuda_bf16.h>
#include <math.h>
#include <stdint.h>

#define N_NODES 50000
#define N_EDGES 600000
#define N_BONDS 600000
#define H 128
#define NH 8

// ---------------- scratch ----------------
__device__ float    g_he0 [(size_t)N_EDGES * H];
__device__ float    g_agg [(size_t)N_EDGES * H];
__device__ float    g_agg2[(size_t)N_NODES * H];
__device__ float    g_beta[(size_t)N_EDGES * NH];
__device__ float    g_ex  [(size_t)N_EDGES * NH];
__device__ float    g_den [(size_t)N_NODES * NH];
__device__ unsigned g_nmax[(size_t)N_NODES * NH];
// 10 weight 128x128 K-slices, each stored transposed [n][k] bf16: [hi 32KB][lo 32KB]
__device__ unsigned char g_wsplit[10 * 2 * 32768];

__device__ __forceinline__ unsigned fflip(float f) {
    unsigned u = __float_as_uint(f);
    return (u & 0x80000000u) ? ~u : (u | 0x80000000u);
}
__device__ __forceinline__ float funflip(unsigned u) {
    return __uint_as_float((u & 0x80000000u) ? (u ^ 0x80000000u) : ~u);
}
__device__ __forceinline__ void split_bf16(float v, unsigned short& hi, unsigned short& lo) {
    __nv_bfloat16 h = __float2bfloat16_rn(v);
    float r = v - __bfloat162float(h);
    __nv_bfloat16 l = __float2bfloat16_rn(r);
    hi = __bfloat16_as_ushort(h);
    lo = __bfloat16_as_ushort(l);
}
__device__ __forceinline__ uint32_t smem_u32(const void* p) {
    uint32_t a;
    asm("{ .reg .u64 t; cvta.to.shared.u64 t, %1; cvt.u32.u64 %0, t; }" : "=r"(a) : "l"(p));
    return a;
}
__device__ __forceinline__ void mma_bf16(float* d, const unsigned* a, unsigned b0, unsigned b1) {
    asm volatile(
        "mma.sync.aligned.m16n8k16.row.col.f32.bf16.bf16.f32 "
        "{%0,%1,%2,%3}, {%4,%5,%6,%7}, {%8,%9}, {%0,%1,%2,%3};"
        : "+f"(d[0]), "+f"(d[1]), "+f"(d[2]), "+f"(d[3])
        : "r"(a[0]), "r"(a[1]), "r"(a[2]), "r"(a[3]), "r"(b0), "r"(b1));
}
__device__ __forceinline__ void ldmx4(unsigned& r0, unsigned& r1, unsigned& r2, unsigned& r3,
                                      uint32_t addr) {
    asm volatile("ldmatrix.sync.aligned.m8n8.x4.shared.b16 {%0,%1,%2,%3}, [%4];"
                 : "=r"(r0), "=r"(r1), "=r"(r2), "=r"(r3) : "r"(addr));
}
#define CP_ASYNC16(sm_, gp_) \
    asm volatile("cp.async.ca.shared.global [%0], [%1], 16;" :: "r"(sm_), "l"(gp_))
#define CP_COMMIT() asm volatile("cp.async.commit_group;" ::: "memory")
#define CP_WAIT0()  asm volatile("cp.async.wait_group 0;" ::: "memory")

__global__ __launch_bounds__(256) void zero_scratch() {
    size_t idx = (size_t)blockIdx.x * 256 + threadIdx.x;
    if (idx < (size_t)N_EDGES * H) g_agg[idx] = 0.f;
    if (idx < (size_t)N_NODES * H) g_agg2[idx] = 0.f;
    if (idx < (size_t)N_NODES * NH) { g_den[idx] = 0.f; g_nmax[idx] = 0x007FFFFFu; }
}

// ---------------- weight prep (all 10 slices in one launch) ----------------
struct WSrcs { const float* p[10]; };

__global__ __launch_bounds__(256) void prep_all(WSrcs ws, unsigned char* dst)
{
    int slice = blockIdx.x >> 6;
    int e = (blockIdx.x & 63) * 256 + threadIdx.x;
    int k = e >> 7;
    int n = e & 127;
    float v = ws.p[slice][k * 128 + n];
    unsigned short h, l;
    split_bf16(v, h, l);
    unsigned short* dsthi = (unsigned short*)(dst + (size_t)slice * 65536);
    unsigned short* dstlo = (unsigned short*)(dst + (size_t)slice * 65536 + 32768);
    dsthi[n * 128 + k] = h;
    dstlo[n * 128 + k] = l;
}

// ==================================================================================
// split-bf16 HMMA GEMM: BM=128, BN=128, BK=32, 256 thr, ldmatrix + double buffer
// B via cp.async from pre-split bf16; A converted inline; 2 CTAs/SM target.
// ==================================================================================
#define SROW 40
#define PLANE (128 * SROW)
#define SMEM_GEMM_BYTES (2 * 2 * PLANE * 2 * 2)

template<int NSEG>
__global__ __launch_bounds__(256, 2)
void mma_gemm(
    int M,
    const float* __restrict__ S0, const int* __restrict__ I0,
    const float* __restrict__ S1, const int* __restrict__ I1,
    const float* __restrict__ S2,
    const unsigned char* __restrict__ wsl,
    const float* __restrict__ B0, const float* __restrict__ B1, const float* __restrict__ B2,
    const float* __restrict__ residual,
    float* __restrict__ out)
{
    extern __shared__ __align__(16) unsigned short smem[];
    unsigned short* sA = smem;
    unsigned short* sB = smem + 2 * 2 * PLANE;
    __shared__ int sI0[128], sI1[128];
    __shared__ float sbias[128];

    const int t = threadIdx.x;
    const int lane = t & 31;
    const int wid = t >> 5;
    const int warp_m = wid & 3;
    const int warp_n = wid >> 2;
    const int blockRow = blockIdx.x * 128;

    if (t < 128) {
        int r = blockRow + t;
        if (r >= M) r = M - 1;
        sI0[t] = I0 ? I0[r] : r;
        sI1[t] = I1 ? I1[r] : r;
        float b = B0[t];
        if (B1) b += B1[t];
        if (B2) b += B2[t];
        sbias[t] = b;
    }
    __syncthreads();

    const int arow = t >> 1;
    const int aseg = t & 1;
    const int arow_cl = (blockRow + arow < M) ? (blockRow + arow) : (M - 1);
    const int bh = t >> 7;
    const int bn = t & 127;

    const uint32_t sa_u32 = smem_u32(sA);
    const uint32_t sb_u32 = smem_u32(sB);
    // B smem byte base for this thread's row (per stage add stage*2*PLANE*2)
    const uint32_t sb_row = sb_u32 + (uint32_t)bh * PLANE * 2 + (uint32_t)bn * SROW * 2;

    float d[2][8][4];
#pragma unroll
    for (int mt = 0; mt < 2; ++mt)
#pragma unroll
        for (int nt = 0; nt < 8; ++nt)
#pragma unroll
            for (int c = 0; c < 4; ++c) d[mt][nt][c] = 0.f;

    const int NITER = NSEG * 4;

    unsigned uhA[8], ulA[8];   // packed bf16 A prefetch (hi/lo)

    // ---- A global load + inline split ----
#define LOAD_A(kt_) do { \
        int s_ = (kt_) >> 2; \
        const float* rp_; \
        if (s_ == 0)      rp_ = S0 + (size_t)sI0[arow] * H; \
        else if (s_ == 1) rp_ = S1 + (size_t)sI1[arow] * H; \
        else              rp_ = S2 + (size_t)arow_cl * H; \
        int kloc_ = ((kt_) & 3) * 32 + aseg * 16; \
        _Pragma("unroll") \
        for (int i_ = 0; i_ < 4; ++i_) { \
            float4 v_ = *(const float4*)(rp_ + kloc_ + i_ * 4); \
            unsigned short h0_, l0_, h1_, l1_; \
            split_bf16(v_.x, h0_, l0_); split_bf16(v_.y, h1_, l1_); \
            uhA[i_ * 2]     = (unsigned)h0_ | ((unsigned)h1_ << 16); \
            ulA[i_ * 2]     = (unsigned)l0_ | ((unsigned)l1_ << 16); \
            split_bf16(v_.z, h0_, l0_); split_bf16(v_.w, h1_, l1_); \
            uhA[i_ * 2 + 1] = (unsigned)h0_ | ((unsigned)h1_ << 16); \
            ulA[i_ * 2 + 1] = (unsigned)l0_ | ((unsigned)l1_ << 16); \
        } \
    } while (0)

#define STORE_A(stage_) do { \
        unsigned short* ah_ = sA + (size_t)(stage_) * 2 * PLANE + (size_t)arow * SROW + aseg * 16; \
        unsigned short* al_ = ah_ + PLANE; \
        *(uint4*)(ah_)     = make_uint4(uhA[0], uhA[1], uhA[2], uhA[3]); \
        *(uint4*)(ah_ + 8) = make_uint4(uhA[4], uhA[5], uhA[6], uhA[7]); \
        *(uint4*)(al_)     = make_uint4(ulA[0], ulA[1], ulA[2], ulA[3]); \
        *(uint4*)(al_ + 8) = make_uint4(ulA[4], ulA[5], ulA[6], ulA[7]); \
    } while (0)

    // ---- B via cp.async: 4 x 16B per thread per stage ----
#define LOAD_B(kt_, stage_) do { \
        int s_ = (kt_) >> 2; \
        const unsigned char* src_ = wsl + (size_t)s_ * 65536 + (size_t)bh * 32768 \
                                  + (size_t)bn * 256 + (size_t)((kt_) & 3) * 64; \
        uint32_t dst_ = sb_row + (uint32_t)(stage_) * 2 * PLANE * 2; \
        CP_ASYNC16(dst_,      src_); \
        CP_ASYNC16(dst_ + 16, src_ + 16); \
        CP_ASYNC16(dst_ + 32, src_ + 32); \
        CP_ASYNC16(dst_ + 48, src_ + 48); \
        CP_COMMIT(); \
    } while (0)

    LOAD_B(0, 0);
    LOAD_A(0);
    STORE_A(0);
    CP_WAIT0();
    __syncthreads();

    for (int kt = 0; kt < NITER; ++kt) {
        const int stage = kt & 1;
        if (kt + 1 < NITER) {
            LOAD_B(kt + 1, (kt + 1) & 1);
            LOAD_A(kt + 1);
        }

        const uint32_t aplane = sa_u32 + (uint32_t)stage * 2 * PLANE * 2;
        const uint32_t bplane = sb_u32 + (uint32_t)stage * 2 * PLANE * 2;
        const uint32_t lrow = (lane & 15);
        const uint32_t lcol = (lane >> 4) * 8;

#pragma unroll
        for (int ks = 0; ks < 2; ++ks) {
            unsigned af[2][2][4];
#pragma unroll
            for (int hl = 0; hl < 2; ++hl)
#pragma unroll
                for (int mt = 0; mt < 2; ++mt) {
                    uint32_t row = warp_m * 32 + mt * 16 + lrow;
                    uint32_t addr = aplane + (uint32_t)hl * PLANE * 2
                                  + (row * SROW + ks * 16 + lcol) * 2;
                    ldmx4(af[hl][mt][0], af[hl][mt][1], af[hl][mt][2], af[hl][mt][3], addr);
                }
            unsigned bf[2][8][2];
#pragma unroll
            for (int hl = 0; hl < 2; ++hl)
#pragma unroll
                for (int pr = 0; pr < 4; ++pr) {
                    uint32_t row = warp_n * 64 + pr * 16 + lrow;
                    uint32_t addr = bplane + (uint32_t)hl * PLANE * 2
                                  + (row * SROW + ks * 16 + lcol) * 2;
                    unsigned r0, r1, r2, r3;
                    ldmx4(r0, r1, r2, r3, addr);
                    bf[hl][pr * 2][0] = r0;  bf[hl][pr * 2][1] = r2;
                    bf[hl][pr * 2 + 1][0] = r1;  bf[hl][pr * 2 + 1][1] = r3;
                }
#pragma unroll
            for (int nt = 0; nt < 8; ++nt)
#pragma unroll
                for (int mt = 0; mt < 2; ++mt) {
                    mma_bf16(d[mt][nt], af[0][mt], bf[0][nt][0], bf[0][nt][1]);
                    mma_bf16(d[mt][nt], af[1][mt], bf[0][nt][0], bf[0][nt][1]);
                    mma_bf16(d[mt][nt], af[0][mt], bf[1][nt][0], bf[1][nt][1]);
                }
        }

        if (kt + 1 < NITER) {
            STORE_A((kt + 1) & 1);
            CP_WAIT0();
            __syncthreads();
        }
    }
#undef LOAD_A
#undef STORE_A
#undef LOAD_B

#pragma unroll
    for (int mt = 0; mt < 2; ++mt) {
#pragma unroll
        for (int half = 0; half < 2; ++half) {
            int r = warp_m * 32 + mt * 16 + (lane >> 2) + half * 8;
            int grow = blockRow + r;
            if (grow >= M) continue;
#pragma unroll
            for (int nt = 0; nt < 8; ++nt) {
                int gc = warp_n * 64 + nt * 8 + (lane & 3) * 2;
                float v0 = d[mt][nt][half * 2 + 0] + sbias[gc];
                float v1 = d[mt][nt][half * 2 + 1] + sbias[gc + 1];
                v0 = fmaxf(v0, 0.f);
                v1 = fmaxf(v1, 0.f);
                if (residual) {
                    float2 rr = *(const float2*)(residual + (size_t)grow * H + gc);
                    v0 += rr.x;
                    v1 += rr.y;
                }
                *(float2*)(out + (size_t)grow * H + gc) = make_float2(v0, v1);
            }
        }
    }
}

// ---------------- bond scatter (float4 per thread) ----------------
__global__ __launch_bounds__(256) void scatter_bond(
    const int* __restrict__ bsrc, const int* __restrict__ btgt,
    const float* __restrict__ battr)
{
    size_t idx = (size_t)blockIdx.x * 256 + threadIdx.x;
    int b = (int)(idx >> 5);
    int c = (int)(idx & 31) * 4;
    int s = bsrc[b];
    int g = btgt[b];
    float4 hv = *(const float4*)(g_he0 + (size_t)s * H + c);
    float4 bv = *(const float4*)(battr + (size_t)b * H + c);
    float* dst = g_agg + (size_t)g * H + c;
    atomicAdd(dst + 0, hv.x * bv.x);
    atomicAdd(dst + 1, hv.y * bv.y);
    atomicAdd(dst + 2, hv.z * bv.z);
    atomicAdd(dst + 3, hv.w * bv.w);
}

// ---------------- attention pass 1 ----------------
__global__ __launch_bounds__(256) void attn_beta(
    const float* __restrict__ x,
    const int* __restrict__ src, const int* __restrict__ tgt,
    const float* __restrict__ he,
    const float* __restrict__ attnw, const float* __restrict__ attnb)
{
    int gt = blockIdx.x * 256 + threadIdx.x;
    int e = gt >> 5;
    int lane = gt & 31;
    int s = src[e];
    int g = tgt[e];
    int c = lane * 4;
    int d = c & 15;
    float4 xs = *(const float4*)(x + (size_t)s * H + c);
    float4 hh = *(const float4*)(he + (size_t)e * H + c);
    float4 xt = *(const float4*)(x + (size_t)g * H + c);
    float p = xs.x * hh.x * attnw[d]     + xt.x * attnw[16 + d]
            + xs.y * hh.y * attnw[d + 1] + xt.y * attnw[17 + d]
            + xs.z * hh.z * attnw[d + 2] + xt.z * attnw[18 + d]
            + xs.w * hh.w * attnw[d + 3] + xt.w * attnw[19 + d];
    p += __shfl_xor_sync(0xffffffffu, p, 1);
    p += __shfl_xor_sync(0xffffffffu, p, 2);
    if ((lane & 3) == 0) {
        int h = lane >> 2;
        float b = p + attnb[0];
        b = (b > 0.f) ? b : 0.01f * b;
        g_beta[(size_t)e * NH + h] = b;
        atomicMax(&g_nmax[(size_t)g * NH + h], fflip(b));
    }
}

// ---------------- attention pass 2 ----------------
__global__ __launch_bounds__(256) void attn_den(const int* __restrict__ tgt)
{
    int idx = blockIdx.x * 256 + threadIdx.x;
    if (idx >= N_EDGES * NH) return;
    int e = idx >> 3;
    int h = idx & 7;
    int g = tgt[e];
    float m = funflip(g_nmax[(size_t)g * NH + h]);
    float ex = expf(g_beta[idx] - m);
    g_ex[idx] = ex;
    atomicAdd(&g_den[(size_t)g * NH + h], ex);
}

// ---------------- attention pass 3 (float4 per thread) ----------------
__global__ __launch_bounds__(256) void attn_scatter(
    const float* __restrict__ x,
    const int* __restrict__ src, const int* __restrict__ tgt,
    const float* __restrict__ he)
{
    size_t idx = (size_t)blockIdx.x * 256 + threadIdx.x;
    int e = (int)(idx >> 5);
    int c = (int)(idx & 31) * 4;
    int h = c >> 4;
    int s = src[e];
    int g = tgt[e];
    float alpha = g_ex[(size_t)e * NH + h] / (g_den[(size_t)g * NH + h] + 1e-16f);
    float4 xv = *(const float4*)(x + (size_t)s * H + c);
    float4 hv = *(const float4*)(he + (size_t)e * H + c);
    float* dst = g_agg2 + (size_t)g * H + c;
    atomicAdd(dst + 0, alpha * xv.x * hv.x);
    atomicAdd(dst + 1, alpha * xv.y * hv.y);
    atomicAdd(dst + 2, alpha * xv.z * hv.z);
    atomicAdd(dst + 3, alpha * xv.w * hv.w);
}

// ---------------- launch ----------------
extern "C" void kernel_launch(void* const* d_in, const int* in_sizes, int n_in,
                              void* d_out, int out_size)
{
    const float* x     = (const float*)d_in[0];
    const int*   ei    = (const int*)d_in[1];
    const float* eattr = (const float*)d_in[2];
    const int*   bei   = (const int*)d_in[3];
    const float* battr = (const float*)d_in[4];
    const float* W_n2e = (const float*)d_in[5];
    const float* b_n2e = (const float*)d_in[6];
    const float* A1w   = (const float*)d_in[7];
    const float* A1b   = (const float*)d_in[8];
    const float* A2w   = (const float*)d_in[9];
    const float* A2b   = (const float*)d_in[10];
    const float* A3w   = (const float*)d_in[11];
    const float* A3b   = (const float*)d_in[12];
    const float* Wc1w  = (const float*)d_in[13];
    const float* Wc1b  = (const float*)d_in[14];
    const float* attnw = (const float*)d_in[15];
    const float* attnb = (const float*)d_in[16];
    const float* Wc2w  = (const float*)d_in[17];
    const float* Wc2b  = (const float*)d_in[18];

    float* out    = (float*)d_out;
    float* out_hx = out;
    float* out_he = out + (size_t)N_NODES * H;
    float* out_ha = out_he + (size_t)N_EDGES * H;

    const int* src  = ei;
    const int* tgt  = ei + N_EDGES;
    const int* bsrc = bei;
    const int* btgt = bei + N_BONDS;

    float *p_he0, *p_agg, *p_agg2;
    unsigned char* p_w;
    cudaGetSymbolAddress((void**)&p_he0,  g_he0);
    cudaGetSymbolAddress((void**)&p_agg,  g_agg);
    cudaGetSymbolAddress((void**)&p_agg2, g_agg2);
    cudaGetSymbolAddress((void**)&p_w,    g_wsplit);

    static cudaStream_t s1 = nullptr;
    static cudaEvent_t evStart, evZ, evA, evB;
    if (!s1) {
        cudaStreamCreateWithFlags(&s1, cudaStreamNonBlocking);
        cudaEventCreateWithFlags(&evStart, cudaEventDisableTiming);
        cudaEventCreateWithFlags(&evZ, cudaEventDisableTiming);
        cudaEventCreateWithFlags(&evA, cudaEventDisableTiming);
        cudaEventCreateWithFlags(&evB, cudaEventDisableTiming);
        cudaFuncSetAttribute(mma_gemm<2>, cudaFuncAttributeMaxDynamicSharedMemorySize, SMEM_GEMM_BYTES);
        cudaFuncSetAttribute(mma_gemm<3>, cudaFuncAttributeMaxDynamicSharedMemorySize, SMEM_GEMM_BYTES);
    }

    WSrcs ws;
    ws.p[0] = W_n2e; ws.p[1] = W_n2e + 128 * H; ws.p[2] = W_n2e + 256 * H;
    ws.p[3] = Wc1w;  ws.p[4] = Wc1w + 128 * H;
    ws.p[5] = A1w;   ws.p[6] = A2w;   ws.p[7] = A3w;
    ws.p[8] = Wc2w;  ws.p[9] = Wc2w + 128 * H;
    prep_all<<<640, 256>>>(ws, p_w);

    cudaEventRecord(evStart, 0);
    cudaStreamWaitEvent(s1, evStart, 0);
    zero_scratch<<<(N_EDGES * H) / 256, 256, 0, s1>>>();
    cudaEventRecord(evZ, s1);

    // 1) he0 = relu(cat(x[src], x[tgt], edge_attr) @ W_n2e + b)   [main]
    mma_gemm<3><<<(N_EDGES + 127) / 128, 256, SMEM_GEMM_BYTES>>>(
        N_EDGES, x, src, x, tgt, eattr, p_w + 0 * 65536,
        b_n2e, nullptr, nullptr, nullptr, p_he0);
    cudaEventRecord(evA, 0);

    // 4) ha GEMM on side stream, concurrent with scatter/he/attention
    cudaStreamWaitEvent(s1, evA, 0);
    mma_gemm<3><<<(N_BONDS + 127) / 128, 256, SMEM_GEMM_BYTES, s1>>>(
        N_BONDS, p_he0, bsrc, p_he0, btgt, battr, p_w + 5 * 65536,
        A1b, A2b, A3b, battr, out_ha);
    cudaEventRecord(evB, s1);

    cudaStreamWaitEvent(0, evZ, 0);

    // 2) agg[btgt] += he0[bsrc] * bond_attr
    scatter_bond<<<(N_BONDS * 32) / 256, 256>>>(bsrc, btgt, battr);

    // 3) he = relu(cat(he0, agg) @ Wc1 + b)
    mma_gemm<2><<<(N_EDGES + 127) / 128, 256, SMEM_GEMM_BYTES>>>(
        N_EDGES, p_he0, nullptr, p_agg, nullptr, nullptr, p_w + 3 * 65536,
        Wc1b, nullptr, nullptr, nullptr, out_he);

    // 5-7) attention
    attn_beta<<<(N_EDGES * 32) / 256, 256>>>(x, src, tgt, out_he, attnw, attnb);
    attn_den<<<(N_EDGES * NH + 255) / 256, 256>>>(tgt);
    attn_scatter<<<(N_EDGES * 32) / 256, 256>>>(x, src, tgt, out_he);

    // 8) hx = relu(cat(x, agg2) @ Wc2 + b)
    mma_gemm<2><<<(N_NODES + 127) / 128, 256, SMEM_GEMM_BYTES>>>(
        N_NODES, x, nullptr, p_agg2, nullptr, nullptr, p_w + 8 * 65536,
        Wc2b, nullptr, nullptr, nullptr, out_hx);

    cudaStreamWaitEvent(0, evB, 0);
}